// round 2
// baseline (speedup 1.0000x reference)
#include <cuda_runtime.h>
#include <math.h>

#define S_LEN 2048
#define HID   4096
#define NH    32
#define NKV   8
#define HD    128
#define GROUPS (NH / NKV)

// ---------------- scratch (static, allocation-free) ----------------
__device__ float g_Q[S_LEN * NH * HD];   // 2048 x 4096
__device__ float g_K[S_LEN * NKV * HD];  // 2048 x 1024
__device__ float g_V[S_LEN * NKV * HD];  // 2048 x 1024
__device__ float g_O[S_LEN * NH * HD];   // 2048 x 4096

// ---------------- GEMM  C[M,N] = A[M,K] * B[N,K]^T  (NT, fp32) -----
// Tiles: BM=BN=64, BK=16. 128 threads, each computes 8x4 outputs.
__global__ __launch_bounds__(128) void sgemm_nt(
    const float* __restrict__ A, const float* __restrict__ B,
    float* __restrict__ C, int M, int N, int K)
{
    __shared__ float As[16][64];
    __shared__ float Bs[16][64];

    const int tid  = threadIdx.x;
    const int trow = tid >> 4;   // 0..7  -> rows trow*8..+7
    const int tcol = tid & 15;   // 0..15 -> cols tcol*4..+3
    const int m0 = blockIdx.y * 64;
    const int n0 = blockIdx.x * 64;

    const float* Ab = A + (size_t)m0 * K;
    const float* Bb = B + (size_t)n0 * K;

    float acc[8][4];
#pragma unroll
    for (int i = 0; i < 8; i++)
#pragma unroll
        for (int j = 0; j < 4; j++) acc[i][j] = 0.f;

    const int lrow0 = tid >> 2;        // 0..31
    const int lc4   = (tid & 3) << 2;  // 0,4,8,12

    for (int k0 = 0; k0 < K; k0 += 16) {
#pragma unroll
        for (int i = 0; i < 2; i++) {
            int row = lrow0 + 32 * i;
            float4 a = *reinterpret_cast<const float4*>(Ab + (size_t)row * K + k0 + lc4);
            As[lc4 + 0][row] = a.x; As[lc4 + 1][row] = a.y;
            As[lc4 + 2][row] = a.z; As[lc4 + 3][row] = a.w;
            float4 b = *reinterpret_cast<const float4*>(Bb + (size_t)row * K + k0 + lc4);
            Bs[lc4 + 0][row] = b.x; Bs[lc4 + 1][row] = b.y;
            Bs[lc4 + 2][row] = b.z; Bs[lc4 + 3][row] = b.w;
        }
        __syncthreads();
#pragma unroll
        for (int kk = 0; kk < 16; kk++) {
            float a[8], b[4];
#pragma unroll
            for (int i = 0; i < 8; i++) a[i] = As[kk][trow * 8 + i];
#pragma unroll
            for (int j = 0; j < 4; j++) b[j] = Bs[kk][tcol * 4 + j];
#pragma unroll
            for (int i = 0; i < 8; i++)
#pragma unroll
                for (int j = 0; j < 4; j++)
                    acc[i][j] = fmaf(a[i], b[j], acc[i][j]);
        }
        __syncthreads();
    }

#pragma unroll
    for (int i = 0; i < 8; i++) {
        float4 o = make_float4(acc[i][0], acc[i][1], acc[i][2], acc[i][3]);
        *reinterpret_cast<float4*>(C + (size_t)(m0 + trow * 8 + i) * N + n0 + tcol * 4) = o;
    }
}

// ---------------- RoPE (in place on [S, nheads, HD]) ----------------
// 64 threads/block, each handles pair (d, d+64) of one (s, h) row.
__global__ void rope_kernel(float* __restrict__ X, int nheads)
{
    int s = blockIdx.x / nheads;
    int h = blockIdx.x % nheads;
    int d = threadIdx.x;  // 0..63

    // inv_freq = theta^(-(2d)/HD), in double for safety
    float inv_freq = (float)exp(-(double)(2 * d) / (double)HD * log(10000.0));
    float ang = (float)s * inv_freq;
    float sn, cs;
    sincosf(ang, &sn, &cs);

    size_t base = ((size_t)s * nheads + h) * HD;
    float x1 = X[base + d];
    float x2 = X[base + d + 64];
    X[base + d]      = x1 * cs - x2 * sn;
    X[base + d + 64] = x2 * cs + x1 * sn;
}

// ---------------- Causal GQA flash attention ------------------------
// Grid (S/8, NH), block = 256 threads (8 warps). Warp w handles q row
// q0+w of head blockIdx.y. K/V staged in 64-key smem tiles.
#define TK 64
__global__ __launch_bounds__(256) void attn_kernel()
{
    const int warp = threadIdx.x >> 5;
    const int lane = threadIdx.x & 31;
    const int h    = blockIdx.y;
    const int kvh  = h / GROUPS;
    const int q0   = blockIdx.x * 8;
    const int r    = q0 + warp;

    __shared__ float Ks[TK][HD];  // 32 KB
    __shared__ float Vs[TK][HD];  // 32 KB

    const float scale = 0.08838834764831845f;  // 1/sqrt(128)

    // q row: lane owns dims lane*4..lane*4+3, pre-scaled
    float4 qv = *reinterpret_cast<const float4*>(
        g_Q + ((size_t)r * NH + h) * HD + lane * 4);
    float q0r = qv.x * scale, q1r = qv.y * scale,
          q2r = qv.z * scale, q3r = qv.w * scale;

    float m = -1e30f, l = 0.f;
    float acc0 = 0.f, acc1 = 0.f, acc2 = 0.f, acc3 = 0.f;

    const int kend = q0 + 8;  // max key+1 needed by any warp in CTA
    for (int kb = 0; kb < kend; kb += TK) {
        __syncthreads();
        // cooperative tile load: 64*128 floats each for K and V
        for (int f = threadIdx.x; f < TK * HD / 4; f += 256) {
            int row = f >> 5;            // /32 float4 per row
            int c   = (f & 31) << 2;
            *reinterpret_cast<float4*>(&Ks[row][c]) =
                *reinterpret_cast<const float4*>(
                    g_K + ((size_t)(kb + row) * NKV + kvh) * HD + c);
            *reinterpret_cast<float4*>(&Vs[row][c]) =
                *reinterpret_cast<const float4*>(
                    g_V + ((size_t)(kb + row) * NKV + kvh) * HD + c);
        }
        __syncthreads();

        int jmax = r - kb + 1;
        if (jmax > TK) jmax = TK;
        for (int j = 0; j < jmax; j++) {
            float4 kv = *reinterpret_cast<const float4*>(&Ks[j][lane * 4]);
            float s = q0r * kv.x + q1r * kv.y + q2r * kv.z + q3r * kv.w;
            s += __shfl_xor_sync(0xffffffffu, s, 16);
            s += __shfl_xor_sync(0xffffffffu, s, 8);
            s += __shfl_xor_sync(0xffffffffu, s, 4);
            s += __shfl_xor_sync(0xffffffffu, s, 2);
            s += __shfl_xor_sync(0xffffffffu, s, 1);

            float mn   = fmaxf(m, s);
            float corr = __expf(m - mn);
            float p    = __expf(s - mn);
            l = l * corr + p;

            float4 vv = *reinterpret_cast<const float4*>(&Vs[j][lane * 4]);
            acc0 = acc0 * corr + p * vv.x;
            acc1 = acc1 * corr + p * vv.y;
            acc2 = acc2 * corr + p * vv.z;
            acc3 = acc3 * corr + p * vv.w;
            m = mn;
        }
    }

    float inv = 1.f / l;
    float4 o = make_float4(acc0 * inv, acc1 * inv, acc2 * inv, acc3 * inv);
    *reinterpret_cast<float4*>(g_O + ((size_t)r * NH + h) * HD + lane * 4) = o;
}

// ---------------- launch ---------------------------------------------
extern "C" void kernel_launch(void* const* d_in, const int* in_sizes, int n_in,
                              void* d_out, int out_size)
{
    const float* hidden = (const float*)d_in[0];
    const float* Wq     = (const float*)d_in[1];
    const float* Wk     = (const float*)d_in[2];
    const float* Wv     = (const float*)d_in[3];
    const float* Wo     = (const float*)d_in[4];
    float* out = (float*)d_out;

    float *pQ, *pK, *pV, *pO;
    cudaGetSymbolAddress((void**)&pQ, g_Q);
    cudaGetSymbolAddress((void**)&pK, g_K);
    cudaGetSymbolAddress((void**)&pV, g_V);
    cudaGetSymbolAddress((void**)&pO, g_O);

    // 1. QKV projections (NT GEMMs)
    {
        dim3 blk(128);
        dim3 gq(NH * HD / 64,  S_LEN / 64);
        dim3 gk(NKV * HD / 64, S_LEN / 64);
        sgemm_nt<<<gq, blk>>>(hidden, Wq, pQ, S_LEN, NH * HD,  HID);
        sgemm_nt<<<gk, blk>>>(hidden, Wk, pK, S_LEN, NKV * HD, HID);
        sgemm_nt<<<gk, blk>>>(hidden, Wv, pV, S_LEN, NKV * HD, HID);
    }

    // 2. RoPE on Q and K
    rope_kernel<<<S_LEN * NH,  64>>>(pQ, NH);
    rope_kernel<<<S_LEN * NKV, 64>>>(pK, NKV);

    // 3. Causal GQA attention
    {
        dim3 grid(S_LEN / 8, NH);
        attn_kernel<<<grid, 256>>>();
    }

    // 4. Output projection
    {
        dim3 blk(128);
        dim3 go(HID / 64, S_LEN / 64);
        sgemm_nt<<<go, blk>>>(pO, Wo, out, S_LEN, HID, HID);
    }
}

// round 3
// speedup vs baseline: 1.6577x; 1.6577x over previous
#include <cuda_runtime.h>
#include <math.h>

#define S_LEN 2048
#define HID   4096
#define NH    32
#define NKV   8
#define HD    128
#define GROUPS (NH / NKV)

// ---------------- scratch (static, allocation-free) ----------------
__device__ float g_Q[S_LEN * NH * HD];   // 2048 x 4096
__device__ float g_K[S_LEN * NKV * HD];  // 2048 x 1024
__device__ float g_V[S_LEN * NKV * HD];  // 2048 x 1024
__device__ float g_O[S_LEN * NH * HD];   // 2048 x 4096

// =====================================================================
// TF32 tensor-core GEMM:  C[M,N] = A[M,K] * B[N,K]^T   (A,B,C fp32)
// CTA tile 128x128, BK=16, 256 threads (8 warps, 2x4), warp tile 64x32.
// mma.sync.aligned.m16n8k8.row.col.f32.tf32.tf32.f32
// Inputs converted to tf32 with round-to-nearest at smem-store time.
// =====================================================================
#define BK 16
#define LSTR 20   // BK + 4 pad -> conflict-free fragment LDS

__device__ __forceinline__ unsigned f2tf(float f) {
    unsigned u;
    asm("cvt.rna.tf32.f32 %0, %1;" : "=r"(u) : "f"(f));
    return u;
}

#define MMA_TF32(d, a, b)                                                 \
    asm volatile(                                                         \
        "mma.sync.aligned.m16n8k8.row.col.f32.tf32.tf32.f32 "             \
        "{%0,%1,%2,%3},{%4,%5,%6,%7},{%8,%9},{%0,%1,%2,%3};"              \
        : "+f"(d[0]), "+f"(d[1]), "+f"(d[2]), "+f"(d[3])                  \
        : "r"(a[0]), "r"(a[1]), "r"(a[2]), "r"(a[3]),                     \
          "r"(b[0]), "r"(b[1]))

__global__ __launch_bounds__(256) void sgemm_tf32(
    const float* __restrict__ A, const float* __restrict__ B,
    float* __restrict__ C, int M, int N, int K)
{
    __shared__ unsigned As[2][128][LSTR];
    __shared__ unsigned Bs[2][128][LSTR];

    const int tid  = threadIdx.x;
    const int warp = tid >> 5;
    const int lane = tid & 31;
    const int wm = (warp >> 2) * 64;   // warp row offset: 0 / 64
    const int wn = (warp & 3)  * 32;   // warp col offset: 0/32/64/96
    const int g  = lane >> 2;          // groupID 0..7
    const int tg = lane & 3;           // thread-in-group 0..3

    const int m0 = blockIdx.y * 128;
    const int n0 = blockIdx.x * 128;

    // staging layout: 512 float4 per tile, 2 per thread (rows r0, r0+64)
    const int r0 = tid >> 2;           // 0..63
    const int c0 = (tid & 3) << 2;     // 0,4,8,12

    const float* Ab = A + (size_t)m0 * K;
    const float* Bb = B + (size_t)n0 * K;

    float acc[4][4][4];
#pragma unroll
    for (int i = 0; i < 4; i++)
#pragma unroll
        for (int j = 0; j < 4; j++)
#pragma unroll
            for (int c = 0; c < 4; c++) acc[i][j][c] = 0.f;

    float4 pa0, pa1, pb0, pb1;
    pa0 = *reinterpret_cast<const float4*>(Ab + (size_t)r0 * K + c0);
    pa1 = *reinterpret_cast<const float4*>(Ab + (size_t)(r0 + 64) * K + c0);
    pb0 = *reinterpret_cast<const float4*>(Bb + (size_t)r0 * K + c0);
    pb1 = *reinterpret_cast<const float4*>(Bb + (size_t)(r0 + 64) * K + c0);

    {   // store buffer 0
        unsigned* a0p = &As[0][r0][c0];
        a0p[0] = f2tf(pa0.x); a0p[1] = f2tf(pa0.y); a0p[2] = f2tf(pa0.z); a0p[3] = f2tf(pa0.w);
        unsigned* a1p = &As[0][r0 + 64][c0];
        a1p[0] = f2tf(pa1.x); a1p[1] = f2tf(pa1.y); a1p[2] = f2tf(pa1.z); a1p[3] = f2tf(pa1.w);
        unsigned* b0p = &Bs[0][r0][c0];
        b0p[0] = f2tf(pb0.x); b0p[1] = f2tf(pb0.y); b0p[2] = f2tf(pb0.z); b0p[3] = f2tf(pb0.w);
        unsigned* b1p = &Bs[0][r0 + 64][c0];
        b1p[0] = f2tf(pb1.x); b1p[1] = f2tf(pb1.y); b1p[2] = f2tf(pb1.z); b1p[3] = f2tf(pb1.w);
    }
    __syncthreads();

    const int nit = K / BK;
    for (int it = 0; it < nit; it++) {
        const int buf = it & 1;

        if (it + 1 < nit) {
            const int k0 = (it + 1) * BK;
            pa0 = *reinterpret_cast<const float4*>(Ab + (size_t)r0 * K + k0 + c0);
            pa1 = *reinterpret_cast<const float4*>(Ab + (size_t)(r0 + 64) * K + k0 + c0);
            pb0 = *reinterpret_cast<const float4*>(Bb + (size_t)r0 * K + k0 + c0);
            pb1 = *reinterpret_cast<const float4*>(Bb + (size_t)(r0 + 64) * K + k0 + c0);
        }

#pragma unroll
        for (int kk = 0; kk < 2; kk++) {
            const int kb = kk * 8;
            unsigned af[4][4], bf[4][2];
#pragma unroll
            for (int mt = 0; mt < 4; mt++) {
                const int row = wm + mt * 16 + g;
                af[mt][0] = As[buf][row][kb + tg];
                af[mt][1] = As[buf][row + 8][kb + tg];
                af[mt][2] = As[buf][row][kb + tg + 4];
                af[mt][3] = As[buf][row + 8][kb + tg + 4];
            }
#pragma unroll
            for (int nt = 0; nt < 4; nt++) {
                const int row = wn + nt * 8 + g;
                bf[nt][0] = Bs[buf][row][kb + tg];
                bf[nt][1] = Bs[buf][row][kb + tg + 4];
            }
#pragma unroll
            for (int mt = 0; mt < 4; mt++)
#pragma unroll
                for (int nt = 0; nt < 4; nt++)
                    MMA_TF32(acc[mt][nt], af[mt], bf[nt]);
        }

        if (it + 1 < nit) {
            const int nb = buf ^ 1;
            unsigned* a0p = &As[nb][r0][c0];
            a0p[0] = f2tf(pa0.x); a0p[1] = f2tf(pa0.y); a0p[2] = f2tf(pa0.z); a0p[3] = f2tf(pa0.w);
            unsigned* a1p = &As[nb][r0 + 64][c0];
            a1p[0] = f2tf(pa1.x); a1p[1] = f2tf(pa1.y); a1p[2] = f2tf(pa1.z); a1p[3] = f2tf(pa1.w);
            unsigned* b0p = &Bs[nb][r0][c0];
            b0p[0] = f2tf(pb0.x); b0p[1] = f2tf(pb0.y); b0p[2] = f2tf(pb0.z); b0p[3] = f2tf(pb0.w);
            unsigned* b1p = &Bs[nb][r0 + 64][c0];
            b1p[0] = f2tf(pb1.x); b1p[1] = f2tf(pb1.y); b1p[2] = f2tf(pb1.z); b1p[3] = f2tf(pb1.w);
        }
        __syncthreads();
    }

    // epilogue: D fragment -> C
#pragma unroll
    for (int mt = 0; mt < 4; mt++) {
#pragma unroll
        for (int nt = 0; nt < 4; nt++) {
            const int row = m0 + wm + mt * 16 + g;
            const int col = n0 + wn + nt * 8 + tg * 2;
            float2 lo = make_float2(acc[mt][nt][0], acc[mt][nt][1]);
            float2 hi = make_float2(acc[mt][nt][2], acc[mt][nt][3]);
            *reinterpret_cast<float2*>(C + (size_t)row * N + col) = lo;
            *reinterpret_cast<float2*>(C + (size_t)(row + 8) * N + col) = hi;
        }
    }
}

// ---------------- RoPE (in place on [S, nheads, HD]) ----------------
// fp32 exp2f path (was FP64-bound). One thread per (s,h,d<64) pair.
__global__ __launch_bounds__(256) void rope_kernel(float* __restrict__ X, int nheads)
{
    int idx = blockIdx.x * blockDim.x + threadIdx.x;
    int d  = idx & 63;
    int sh = idx >> 6;
    int h  = sh % nheads;
    int s  = sh / nheads;

    // inv_freq = 10000^(-2d/HD) = exp2(-(2d/HD) * log2(10000))
    float inv_freq = exp2f(-(float)(2 * d) * (1.0f / HD) * 13.287712379549449f);
    float ang = (float)s * inv_freq;
    float sn, cs;
    sincosf(ang, &sn, &cs);

    size_t base = ((size_t)s * nheads + h) * HD;
    float x1 = X[base + d];
    float x2 = X[base + d + 64];
    X[base + d]      = x1 * cs - x2 * sn;
    X[base + d + 64] = x2 * cs + x1 * sn;
}

// ---------------- Causal GQA flash attention ------------------------
// Grid (S/8, NH), block = 256 threads (8 warps). Warp w handles q row
// q0+w of head blockIdx.y. K/V staged in 64-key smem tiles.
#define TK 64
__global__ __launch_bounds__(256) void attn_kernel()
{
    const int warp = threadIdx.x >> 5;
    const int lane = threadIdx.x & 31;
    const int h    = blockIdx.y;
    const int kvh  = h / GROUPS;
    const int q0   = blockIdx.x * 8;
    const int r    = q0 + warp;

    __shared__ float Ks[TK][HD];  // 32 KB
    __shared__ float Vs[TK][HD];  // 32 KB

    const float scale = 0.08838834764831845f;  // 1/sqrt(128)

    float4 qv = *reinterpret_cast<const float4*>(
        g_Q + ((size_t)r * NH + h) * HD + lane * 4);
    float q0r = qv.x * scale, q1r = qv.y * scale,
          q2r = qv.z * scale, q3r = qv.w * scale;

    float m = -1e30f, l = 0.f;
    float acc0 = 0.f, acc1 = 0.f, acc2 = 0.f, acc3 = 0.f;

    const int kend = q0 + 8;
    for (int kb = 0; kb < kend; kb += TK) {
        __syncthreads();
        for (int f = threadIdx.x; f < TK * HD / 4; f += 256) {
            int row = f >> 5;
            int c   = (f & 31) << 2;
            *reinterpret_cast<float4*>(&Ks[row][c]) =
                *reinterpret_cast<const float4*>(
                    g_K + ((size_t)(kb + row) * NKV + kvh) * HD + c);
            *reinterpret_cast<float4*>(&Vs[row][c]) =
                *reinterpret_cast<const float4*>(
                    g_V + ((size_t)(kb + row) * NKV + kvh) * HD + c);
        }
        __syncthreads();

        int jmax = r - kb + 1;
        if (jmax > TK) jmax = TK;
        for (int j = 0; j < jmax; j++) {
            float4 kv = *reinterpret_cast<const float4*>(&Ks[j][lane * 4]);
            float s = q0r * kv.x + q1r * kv.y + q2r * kv.z + q3r * kv.w;
            s += __shfl_xor_sync(0xffffffffu, s, 16);
            s += __shfl_xor_sync(0xffffffffu, s, 8);
            s += __shfl_xor_sync(0xffffffffu, s, 4);
            s += __shfl_xor_sync(0xffffffffu, s, 2);
            s += __shfl_xor_sync(0xffffffffu, s, 1);

            float mn   = fmaxf(m, s);
            float corr = __expf(m - mn);
            float p    = __expf(s - mn);
            l = l * corr + p;

            float4 vv = *reinterpret_cast<const float4*>(&Vs[j][lane * 4]);
            acc0 = acc0 * corr + p * vv.x;
            acc1 = acc1 * corr + p * vv.y;
            acc2 = acc2 * corr + p * vv.z;
            acc3 = acc3 * corr + p * vv.w;
            m = mn;
        }
    }

    float inv = 1.f / l;
    float4 o = make_float4(acc0 * inv, acc1 * inv, acc2 * inv, acc3 * inv);
    *reinterpret_cast<float4*>(g_O + ((size_t)r * NH + h) * HD + lane * 4) = o;
}

// ---------------- launch ---------------------------------------------
extern "C" void kernel_launch(void* const* d_in, const int* in_sizes, int n_in,
                              void* d_out, int out_size)
{
    const float* hidden = (const float*)d_in[0];
    const float* Wq     = (const float*)d_in[1];
    const float* Wk     = (const float*)d_in[2];
    const float* Wv     = (const float*)d_in[3];
    const float* Wo     = (const float*)d_in[4];
    float* out = (float*)d_out;

    float *pQ, *pK, *pV, *pO;
    cudaGetSymbolAddress((void**)&pQ, g_Q);
    cudaGetSymbolAddress((void**)&pK, g_K);
    cudaGetSymbolAddress((void**)&pV, g_V);
    cudaGetSymbolAddress((void**)&pO, g_O);

    // 1. QKV projections (tf32 tensor-core NT GEMMs)
    {
        dim3 blk(256);
        dim3 gq(NH * HD / 128,  S_LEN / 128);   // 32 x 16
        dim3 gk(NKV * HD / 128, S_LEN / 128);   // 8 x 16
        sgemm_tf32<<<gq, blk>>>(hidden, Wq, pQ, S_LEN, NH * HD,  HID);
        sgemm_tf32<<<gk, blk>>>(hidden, Wk, pK, S_LEN, NKV * HD, HID);
        sgemm_tf32<<<gk, blk>>>(hidden, Wv, pV, S_LEN, NKV * HD, HID);
    }

    // 2. RoPE on Q and K
    rope_kernel<<<S_LEN * NH  * 64 / 256, 256>>>(pQ, NH);
    rope_kernel<<<S_LEN * NKV * 64 / 256, 256>>>(pK, NKV);

    // 3. Causal GQA attention
    {
        dim3 grid(S_LEN / 8, NH);
        attn_kernel<<<grid, 256>>>();
    }

    // 4. Output projection
    {
        dim3 blk(256);
        dim3 go(HID / 128, S_LEN / 128);        // 32 x 16
        sgemm_tf32<<<go, blk>>>(pO, Wo, out, S_LEN, HID, HID);
    }
}

// round 4
// speedup vs baseline: 4.1567x; 2.5075x over previous
#include <cuda_runtime.h>
#include <math.h>

#define S_LEN 2048
#define HID   4096
#define NH    32
#define NKV   8
#define HD    128
#define GROUPS (NH / NKV)

// ---------------- scratch (static, allocation-free) ----------------
__device__ float g_Q[S_LEN * NH * HD];   // 2048 x 4096
__device__ float g_K[S_LEN * NKV * HD];  // 2048 x 1024
__device__ float g_V[S_LEN * NKV * HD];  // 2048 x 1024
__device__ float g_O[S_LEN * NH * HD];   // 2048 x 4096

// =====================================================================
// TF32 helpers
// =====================================================================
__device__ __forceinline__ unsigned f2tf(float f) {
    unsigned u;
    asm("cvt.rna.tf32.f32 %0, %1;" : "=r"(u) : "f"(f));
    return u;
}

#define MMA_TF32(d, a, b)                                                 \
    asm volatile(                                                         \
        "mma.sync.aligned.m16n8k8.row.col.f32.tf32.tf32.f32 "             \
        "{%0,%1,%2,%3},{%4,%5,%6,%7},{%8,%9},{%0,%1,%2,%3};"              \
        : "+f"(d[0]), "+f"(d[1]), "+f"(d[2]), "+f"(d[3])                  \
        : "r"(a[0]), "r"(a[1]), "r"(a[2]), "r"(a[3]),                     \
          "r"(b[0]), "r"(b[1]))

// =====================================================================
// TF32 tensor-core GEMM:  C[M,N] = A[M,K] * B[N,K]^T   (A,B,C fp32)
// CTA tile 128x128, BK=16, 256 threads (8 warps, 2x4), warp tile 64x32.
// =====================================================================
#define BK 16
#define LSTR 20

__global__ __launch_bounds__(256) void sgemm_tf32(
    const float* __restrict__ A, const float* __restrict__ B,
    float* __restrict__ C, int M, int N, int K)
{
    __shared__ unsigned As[2][128][LSTR];
    __shared__ unsigned Bs[2][128][LSTR];

    const int tid  = threadIdx.x;
    const int warp = tid >> 5;
    const int lane = tid & 31;
    const int wm = (warp >> 2) * 64;
    const int wn = (warp & 3)  * 32;
    const int g  = lane >> 2;
    const int tg = lane & 3;

    const int m0 = blockIdx.y * 128;
    const int n0 = blockIdx.x * 128;

    const int r0 = tid >> 2;
    const int c0 = (tid & 3) << 2;

    const float* Ab = A + (size_t)m0 * K;
    const float* Bb = B + (size_t)n0 * K;

    float acc[4][4][4];
#pragma unroll
    for (int i = 0; i < 4; i++)
#pragma unroll
        for (int j = 0; j < 4; j++)
#pragma unroll
            for (int c = 0; c < 4; c++) acc[i][j][c] = 0.f;

    float4 pa0, pa1, pb0, pb1;
    pa0 = *reinterpret_cast<const float4*>(Ab + (size_t)r0 * K + c0);
    pa1 = *reinterpret_cast<const float4*>(Ab + (size_t)(r0 + 64) * K + c0);
    pb0 = *reinterpret_cast<const float4*>(Bb + (size_t)r0 * K + c0);
    pb1 = *reinterpret_cast<const float4*>(Bb + (size_t)(r0 + 64) * K + c0);

    {
        unsigned* a0p = &As[0][r0][c0];
        a0p[0] = f2tf(pa0.x); a0p[1] = f2tf(pa0.y); a0p[2] = f2tf(pa0.z); a0p[3] = f2tf(pa0.w);
        unsigned* a1p = &As[0][r0 + 64][c0];
        a1p[0] = f2tf(pa1.x); a1p[1] = f2tf(pa1.y); a1p[2] = f2tf(pa1.z); a1p[3] = f2tf(pa1.w);
        unsigned* b0p = &Bs[0][r0][c0];
        b0p[0] = f2tf(pb0.x); b0p[1] = f2tf(pb0.y); b0p[2] = f2tf(pb0.z); b0p[3] = f2tf(pb0.w);
        unsigned* b1p = &Bs[0][r0 + 64][c0];
        b1p[0] = f2tf(pb1.x); b1p[1] = f2tf(pb1.y); b1p[2] = f2tf(pb1.z); b1p[3] = f2tf(pb1.w);
    }
    __syncthreads();

    const int nit = K / BK;
    for (int it = 0; it < nit; it++) {
        const int buf = it & 1;

        if (it + 1 < nit) {
            const int k0 = (it + 1) * BK;
            pa0 = *reinterpret_cast<const float4*>(Ab + (size_t)r0 * K + k0 + c0);
            pa1 = *reinterpret_cast<const float4*>(Ab + (size_t)(r0 + 64) * K + k0 + c0);
            pb0 = *reinterpret_cast<const float4*>(Bb + (size_t)r0 * K + k0 + c0);
            pb1 = *reinterpret_cast<const float4*>(Bb + (size_t)(r0 + 64) * K + k0 + c0);
        }

#pragma unroll
        for (int kk = 0; kk < 2; kk++) {
            const int kb = kk * 8;
            unsigned af[4][4], bf[4][2];
#pragma unroll
            for (int mt = 0; mt < 4; mt++) {
                const int row = wm + mt * 16 + g;
                af[mt][0] = As[buf][row][kb + tg];
                af[mt][1] = As[buf][row + 8][kb + tg];
                af[mt][2] = As[buf][row][kb + tg + 4];
                af[mt][3] = As[buf][row + 8][kb + tg + 4];
            }
#pragma unroll
            for (int nt = 0; nt < 4; nt++) {
                const int row = wn + nt * 8 + g;
                bf[nt][0] = Bs[buf][row][kb + tg];
                bf[nt][1] = Bs[buf][row][kb + tg + 4];
            }
#pragma unroll
            for (int mt = 0; mt < 4; mt++)
#pragma unroll
                for (int nt = 0; nt < 4; nt++)
                    MMA_TF32(acc[mt][nt], af[mt], bf[nt]);
        }

        if (it + 1 < nit) {
            const int nb = buf ^ 1;
            unsigned* a0p = &As[nb][r0][c0];
            a0p[0] = f2tf(pa0.x); a0p[1] = f2tf(pa0.y); a0p[2] = f2tf(pa0.z); a0p[3] = f2tf(pa0.w);
            unsigned* a1p = &As[nb][r0 + 64][c0];
            a1p[0] = f2tf(pa1.x); a1p[1] = f2tf(pa1.y); a1p[2] = f2tf(pa1.z); a1p[3] = f2tf(pa1.w);
            unsigned* b0p = &Bs[nb][r0][c0];
            b0p[0] = f2tf(pb0.x); b0p[1] = f2tf(pb0.y); b0p[2] = f2tf(pb0.z); b0p[3] = f2tf(pb0.w);
            unsigned* b1p = &Bs[nb][r0 + 64][c0];
            b1p[0] = f2tf(pb1.x); b1p[1] = f2tf(pb1.y); b1p[2] = f2tf(pb1.z); b1p[3] = f2tf(pb1.w);
        }
        __syncthreads();
    }

#pragma unroll
    for (int mt = 0; mt < 4; mt++) {
#pragma unroll
        for (int nt = 0; nt < 4; nt++) {
            const int row = m0 + wm + mt * 16 + g;
            const int col = n0 + wn + nt * 8 + tg * 2;
            float2 lo = make_float2(acc[mt][nt][0], acc[mt][nt][1]);
            float2 hi = make_float2(acc[mt][nt][2], acc[mt][nt][3]);
            *reinterpret_cast<float2*>(C + (size_t)row * N + col) = lo;
            *reinterpret_cast<float2*>(C + (size_t)(row + 8) * N + col) = hi;
        }
    }
}

// ---------------- RoPE (in place on [S, nheads, HD]) ----------------
__global__ __launch_bounds__(256) void rope_kernel(float* __restrict__ X, int nheads)
{
    int idx = blockIdx.x * blockDim.x + threadIdx.x;
    int d  = idx & 63;
    int sh = idx >> 6;
    int h  = sh % nheads;
    int s  = sh / nheads;

    float inv_freq = exp2f(-(float)(2 * d) * (1.0f / HD) * 13.287712379549449f);
    float ang = (float)s * inv_freq;
    float sn, cs;
    sincosf(ang, &sn, &cs);

    size_t base = ((size_t)s * nheads + h) * HD;
    float x1 = X[base + d];
    float x2 = X[base + d + 64];
    X[base + d]      = x1 * cs - x2 * sn;
    X[base + d + 64] = x2 * cs + x1 * sn;
}

// =====================================================================
// Tensor-core causal GQA flash attention (tf32 m16n8k8)
// CTA: 64 q rows x 1 head, 4 warps (16 rows/warp). KV tiles of 64 keys.
// Smem: Qs[64][132], Ks[64][132] (bank = 4g+tg, conflict-free),
//       Vs[64][136]  (bank = 8tg+g, conflict-free).
// =====================================================================
#define TK 64
#define QKSTR 132
#define VSTR  136
#define ATT_SMEM_WORDS (64*QKSTR*2 + 64*VSTR)   // 25600 words = 100 KB

__global__ __launch_bounds__(128) void attn_tc_kernel()
{
    extern __shared__ unsigned sm[];
    unsigned* Qs = sm;                    // [64][132]
    unsigned* Ks = sm + 64 * QKSTR;       // [64][132]
    unsigned* Vs = sm + 2 * 64 * QKSTR;   // [64][136]

    const int tid  = threadIdx.x;
    const int warp = tid >> 5;
    const int lane = tid & 31;
    const int g  = lane >> 2;
    const int tg = lane & 3;

    const int h    = blockIdx.y;
    const int kvh  = h / GROUPS;
    const int qt   = (gridDim.x - 1) - blockIdx.x;  // heavy tiles first
    const int qg0  = qt * 64;
    const int wq0  = warp * 16;

    const float scale = 0.08838834764831845f;  // 1/sqrt(128)

    // ---- load Q tile (64 x 128), pre-scaled, tf32 ----
    for (int idx = tid; idx < 64 * 32; idx += 128) {
        int row = idx >> 5;
        int c   = (idx & 31) << 2;
        float4 q = *reinterpret_cast<const float4*>(
            g_Q + ((size_t)(qg0 + row) * NH + h) * HD + c);
        unsigned* p = &Qs[row * QKSTR + c];
        p[0] = f2tf(q.x * scale); p[1] = f2tf(q.y * scale);
        p[2] = f2tf(q.z * scale); p[3] = f2tf(q.w * scale);
    }

    // softmax state (rows g and g+8 of this warp's 16)
    float m0 = -1e30f, m1 = -1e30f, l0 = 0.f, l1 = 0.f;
    float co[16][4];
#pragma unroll
    for (int nt = 0; nt < 16; nt++)
#pragma unroll
        for (int c = 0; c < 4; c++) co[nt][c] = 0.f;

    const int q0row = qg0 + wq0 + g;       // this thread's row A
    const int q1row = q0row + 8;           // row B

    const int ntiles = qt + 1;
    for (int t = 0; t < ntiles; t++) {
        const int kb = t * TK;
        __syncthreads();
        // ---- load K/V tiles ----
        for (int idx = tid; idx < TK * 32; idx += 128) {
            int row = idx >> 5;
            int c   = (idx & 31) << 2;
            float4 kf = *reinterpret_cast<const float4*>(
                g_K + ((size_t)(kb + row) * NKV + kvh) * HD + c);
            unsigned* kp = &Ks[row * QKSTR + c];
            kp[0] = f2tf(kf.x); kp[1] = f2tf(kf.y); kp[2] = f2tf(kf.z); kp[3] = f2tf(kf.w);
            float4 vf = *reinterpret_cast<const float4*>(
                g_V + ((size_t)(kb + row) * NKV + kvh) * HD + c);
            unsigned* vp = &Vs[row * VSTR + c];
            vp[0] = f2tf(vf.x); vp[1] = f2tf(vf.y); vp[2] = f2tf(vf.z); vp[3] = f2tf(vf.w);
        }
        __syncthreads();

        // ---- S = Q K^T  (16 x 64 per warp) ----
        float sc[8][4];
#pragma unroll
        for (int nt = 0; nt < 8; nt++)
#pragma unroll
            for (int c = 0; c < 4; c++) sc[nt][c] = 0.f;

#pragma unroll
        for (int kk = 0; kk < 16; kk++) {
            const int kc = kk * 8;
            unsigned af[4];
            af[0] = Qs[(wq0 + g)     * QKSTR + kc + tg];
            af[1] = Qs[(wq0 + g + 8) * QKSTR + kc + tg];
            af[2] = Qs[(wq0 + g)     * QKSTR + kc + tg + 4];
            af[3] = Qs[(wq0 + g + 8) * QKSTR + kc + tg + 4];
#pragma unroll
            for (int nt = 0; nt < 8; nt++) {
                unsigned bf[2];
                bf[0] = Ks[(nt * 8 + g) * QKSTR + kc + tg];
                bf[1] = Ks[(nt * 8 + g) * QKSTR + kc + tg + 4];
                MMA_TF32(sc[nt], af, bf);
            }
        }

        // ---- causal mask ----
        if (kb + TK - 1 > qg0 + wq0) {
#pragma unroll
            for (int nt = 0; nt < 8; nt++) {
                int kcol = kb + nt * 8 + 2 * tg;
                if (kcol     > q0row) sc[nt][0] = -1e30f;
                if (kcol + 1 > q0row) sc[nt][1] = -1e30f;
                if (kcol     > q1row) sc[nt][2] = -1e30f;
                if (kcol + 1 > q1row) sc[nt][3] = -1e30f;
            }
        }

        // ---- online softmax ----
        float mx0 = -1e30f, mx1 = -1e30f;
#pragma unroll
        for (int nt = 0; nt < 8; nt++) {
            mx0 = fmaxf(mx0, fmaxf(sc[nt][0], sc[nt][1]));
            mx1 = fmaxf(mx1, fmaxf(sc[nt][2], sc[nt][3]));
        }
        mx0 = fmaxf(mx0, __shfl_xor_sync(0xffffffffu, mx0, 1));
        mx0 = fmaxf(mx0, __shfl_xor_sync(0xffffffffu, mx0, 2));
        mx1 = fmaxf(mx1, __shfl_xor_sync(0xffffffffu, mx1, 1));
        mx1 = fmaxf(mx1, __shfl_xor_sync(0xffffffffu, mx1, 2));

        float mn0 = fmaxf(m0, mx0);
        float mn1 = fmaxf(m1, mx1);
        float corr0 = __expf(m0 - mn0);
        float corr1 = __expf(m1 - mn1);

        float rs0 = 0.f, rs1 = 0.f;
#pragma unroll
        for (int nt = 0; nt < 8; nt++) {
            sc[nt][0] = __expf(sc[nt][0] - mn0); rs0 += sc[nt][0];
            sc[nt][1] = __expf(sc[nt][1] - mn0); rs0 += sc[nt][1];
            sc[nt][2] = __expf(sc[nt][2] - mn1); rs1 += sc[nt][2];
            sc[nt][3] = __expf(sc[nt][3] - mn1); rs1 += sc[nt][3];
        }
        rs0 += __shfl_xor_sync(0xffffffffu, rs0, 1);
        rs0 += __shfl_xor_sync(0xffffffffu, rs0, 2);
        rs1 += __shfl_xor_sync(0xffffffffu, rs1, 1);
        rs1 += __shfl_xor_sync(0xffffffffu, rs1, 2);

        l0 = l0 * corr0 + rs0;
        l1 = l1 * corr1 + rs1;
        m0 = mn0; m1 = mn1;

#pragma unroll
        for (int nt = 0; nt < 16; nt++) {
            co[nt][0] *= corr0; co[nt][1] *= corr0;
            co[nt][2] *= corr1; co[nt][3] *= corr1;
        }

        // ---- O += P V  (P transposed C-frag -> A-frag via shfl) ----
        const int srcA = (lane & 28) | (tg >> 1);
        const int srcB = srcA + 2;
#pragma unroll
        for (int kc = 0; kc < 8; kc++) {
            float t0 = __shfl_sync(0xffffffffu, sc[kc][0], srcA);
            float t1 = __shfl_sync(0xffffffffu, sc[kc][1], srcA);
            float t2 = __shfl_sync(0xffffffffu, sc[kc][2], srcA);
            float t3 = __shfl_sync(0xffffffffu, sc[kc][3], srcA);
            float u0 = __shfl_sync(0xffffffffu, sc[kc][0], srcB);
            float u1 = __shfl_sync(0xffffffffu, sc[kc][1], srcB);
            float u2 = __shfl_sync(0xffffffffu, sc[kc][2], srcB);
            float u3 = __shfl_sync(0xffffffffu, sc[kc][3], srcB);
            unsigned af[4];
            af[0] = f2tf((tg & 1) ? t1 : t0);   // (g,   tg)
            af[1] = f2tf((tg & 1) ? t3 : t2);   // (g+8, tg)
            af[2] = f2tf((tg & 1) ? u1 : u0);   // (g,   tg+4)
            af[3] = f2tf((tg & 1) ? u3 : u2);   // (g+8, tg+4)
#pragma unroll
            for (int nt = 0; nt < 16; nt++) {
                unsigned bf[2];
                bf[0] = Vs[(kc * 8 + tg)     * VSTR + nt * 8 + g];
                bf[1] = Vs[(kc * 8 + tg + 4) * VSTR + nt * 8 + g];
                MMA_TF32(co[nt], af, bf);
            }
        }
    }

    // ---- epilogue ----
    float inv0 = 1.f / l0;
    float inv1 = 1.f / l1;
    float* O0 = g_O + ((size_t)q0row * NH + h) * HD;
    float* O1 = g_O + ((size_t)q1row * NH + h) * HD;
#pragma unroll
    for (int nt = 0; nt < 16; nt++) {
        int d = nt * 8 + 2 * tg;
        *reinterpret_cast<float2*>(O0 + d) =
            make_float2(co[nt][0] * inv0, co[nt][1] * inv0);
        *reinterpret_cast<float2*>(O1 + d) =
            make_float2(co[nt][2] * inv1, co[nt][3] * inv1);
    }
}

// ---------------- launch ---------------------------------------------
extern "C" void kernel_launch(void* const* d_in, const int* in_sizes, int n_in,
                              void* d_out, int out_size)
{
    const float* hidden = (const float*)d_in[0];
    const float* Wq     = (const float*)d_in[1];
    const float* Wk     = (const float*)d_in[2];
    const float* Wv     = (const float*)d_in[3];
    const float* Wo     = (const float*)d_in[4];
    float* out = (float*)d_out;

    float *pQ, *pK, *pV, *pO;
    cudaGetSymbolAddress((void**)&pQ, g_Q);
    cudaGetSymbolAddress((void**)&pK, g_K);
    cudaGetSymbolAddress((void**)&pV, g_V);
    cudaGetSymbolAddress((void**)&pO, g_O);

    // 1. QKV projections (tf32 tensor-core NT GEMMs)
    {
        dim3 blk(256);
        dim3 gq(NH * HD / 128,  S_LEN / 128);
        dim3 gk(NKV * HD / 128, S_LEN / 128);
        sgemm_tf32<<<gq, blk>>>(hidden, Wq, pQ, S_LEN, NH * HD,  HID);
        sgemm_tf32<<<gk, blk>>>(hidden, Wk, pK, S_LEN, NKV * HD, HID);
        sgemm_tf32<<<gk, blk>>>(hidden, Wv, pV, S_LEN, NKV * HD, HID);
    }

    // 2. RoPE on Q and K
    rope_kernel<<<S_LEN * NH  * 64 / 256, 256>>>(pQ, NH);
    rope_kernel<<<S_LEN * NKV * 64 / 256, 256>>>(pK, NKV);

    // 3. Tensor-core causal GQA flash attention
    {
        static int smem_set = 0;
        if (!smem_set) {
            cudaFuncSetAttribute(attn_tc_kernel,
                                 cudaFuncAttributeMaxDynamicSharedMemorySize,
                                 ATT_SMEM_WORDS * 4);
            smem_set = 1;
        }
        dim3 grid(S_LEN / 64, NH);
        attn_tc_kernel<<<grid, 128, ATT_SMEM_WORDS * 4>>>();
    }

    // 4. Output projection
    {
        dim3 blk(256);
        dim3 go(HID / 128, S_LEN / 128);
        sgemm_tf32<<<go, blk>>>(pO, Wo, out, S_LEN, HID, HID);
    }
}

// round 5
// speedup vs baseline: 4.1574x; 1.0002x over previous
#include <cuda_runtime.h>
#include <math.h>

#define S_LEN 2048
#define HID   4096
#define NH    32
#define NKV   8
#define HD    128
#define GROUPS (NH / NKV)

// ---------------- scratch (static, allocation-free) ----------------
__device__ float g_Q[S_LEN * NH * HD];   // 2048 x 4096
__device__ float g_K[S_LEN * NKV * HD];  // 2048 x 1024
__device__ float g_V[S_LEN * NKV * HD];  // 2048 x 1024
__device__ float g_O[S_LEN * NH * HD];   // 2048 x 4096

// =====================================================================
// TF32 helpers
// =====================================================================
__device__ __forceinline__ unsigned f2tf(float f) {
    unsigned u;
    asm("cvt.rna.tf32.f32 %0, %1;" : "=r"(u) : "f"(f));
    return u;
}

#define MMA_TF32(d, a, b)                                                 \
    asm volatile(                                                         \
        "mma.sync.aligned.m16n8k8.row.col.f32.tf32.tf32.f32 "             \
        "{%0,%1,%2,%3},{%4,%5,%6,%7},{%8,%9},{%0,%1,%2,%3};"              \
        : "+f"(d[0]), "+f"(d[1]), "+f"(d[2]), "+f"(d[3])                  \
        : "r"(a[0]), "r"(a[1]), "r"(a[2]), "r"(a[3]),                     \
          "r"(b[0]), "r"(b[1]))

// =====================================================================
// TF32 tensor-core GEMM:  C[M,N] = A[M,K] * B[N,K]^T   (A,B,C fp32)
// CTA tile 128x128, BK=16, 256 threads (8 warps, 2x4), warp tile 64x32.
// =====================================================================
#define BK 16
#define LSTR 20

__global__ __launch_bounds__(256) void sgemm_tf32(
    const float* __restrict__ A, const float* __restrict__ B,
    float* __restrict__ C, int M, int N, int K)
{
    __shared__ unsigned As[2][128][LSTR];
    __shared__ unsigned Bs[2][128][LSTR];

    const int tid  = threadIdx.x;
    const int warp = tid >> 5;
    const int lane = tid & 31;
    const int wm = (warp >> 2) * 64;
    const int wn = (warp & 3)  * 32;
    const int g  = lane >> 2;
    const int tg = lane & 3;

    const int m0 = blockIdx.y * 128;
    const int n0 = blockIdx.x * 128;

    const int r0 = tid >> 2;
    const int c0 = (tid & 3) << 2;

    const float* Ab = A + (size_t)m0 * K;
    const float* Bb = B + (size_t)n0 * K;

    float acc[4][4][4];
#pragma unroll
    for (int i = 0; i < 4; i++)
#pragma unroll
        for (int j = 0; j < 4; j++)
#pragma unroll
            for (int c = 0; c < 4; c++) acc[i][j][c] = 0.f;

    float4 pa0, pa1, pb0, pb1;
    pa0 = *reinterpret_cast<const float4*>(Ab + (size_t)r0 * K + c0);
    pa1 = *reinterpret_cast<const float4*>(Ab + (size_t)(r0 + 64) * K + c0);
    pb0 = *reinterpret_cast<const float4*>(Bb + (size_t)r0 * K + c0);
    pb1 = *reinterpret_cast<const float4*>(Bb + (size_t)(r0 + 64) * K + c0);

    {
        unsigned* a0p = &As[0][r0][c0];
        a0p[0] = f2tf(pa0.x); a0p[1] = f2tf(pa0.y); a0p[2] = f2tf(pa0.z); a0p[3] = f2tf(pa0.w);
        unsigned* a1p = &As[0][r0 + 64][c0];
        a1p[0] = f2tf(pa1.x); a1p[1] = f2tf(pa1.y); a1p[2] = f2tf(pa1.z); a1p[3] = f2tf(pa1.w);
        unsigned* b0p = &Bs[0][r0][c0];
        b0p[0] = f2tf(pb0.x); b0p[1] = f2tf(pb0.y); b0p[2] = f2tf(pb0.z); b0p[3] = f2tf(pb0.w);
        unsigned* b1p = &Bs[0][r0 + 64][c0];
        b1p[0] = f2tf(pb1.x); b1p[1] = f2tf(pb1.y); b1p[2] = f2tf(pb1.z); b1p[3] = f2tf(pb1.w);
    }
    __syncthreads();

    const int nit = K / BK;
    for (int it = 0; it < nit; it++) {
        const int buf = it & 1;

        if (it + 1 < nit) {
            const int k0 = (it + 1) * BK;
            pa0 = *reinterpret_cast<const float4*>(Ab + (size_t)r0 * K + k0 + c0);
            pa1 = *reinterpret_cast<const float4*>(Ab + (size_t)(r0 + 64) * K + k0 + c0);
            pb0 = *reinterpret_cast<const float4*>(Bb + (size_t)r0 * K + k0 + c0);
            pb1 = *reinterpret_cast<const float4*>(Bb + (size_t)(r0 + 64) * K + k0 + c0);
        }

#pragma unroll
        for (int kk = 0; kk < 2; kk++) {
            const int kb = kk * 8;
            unsigned af[4][4], bf[4][2];
#pragma unroll
            for (int mt = 0; mt < 4; mt++) {
                const int row = wm + mt * 16 + g;
                af[mt][0] = As[buf][row][kb + tg];
                af[mt][1] = As[buf][row + 8][kb + tg];
                af[mt][2] = As[buf][row][kb + tg + 4];
                af[mt][3] = As[buf][row + 8][kb + tg + 4];
            }
#pragma unroll
            for (int nt = 0; nt < 4; nt++) {
                const int row = wn + nt * 8 + g;
                bf[nt][0] = Bs[buf][row][kb + tg];
                bf[nt][1] = Bs[buf][row][kb + tg + 4];
            }
#pragma unroll
            for (int mt = 0; mt < 4; mt++)
#pragma unroll
                for (int nt = 0; nt < 4; nt++)
                    MMA_TF32(acc[mt][nt], af[mt], bf[nt]);
        }

        if (it + 1 < nit) {
            const int nb = buf ^ 1;
            unsigned* a0p = &As[nb][r0][c0];
            a0p[0] = f2tf(pa0.x); a0p[1] = f2tf(pa0.y); a0p[2] = f2tf(pa0.z); a0p[3] = f2tf(pa0.w);
            unsigned* a1p = &As[nb][r0 + 64][c0];
            a1p[0] = f2tf(pa1.x); a1p[1] = f2tf(pa1.y); a1p[2] = f2tf(pa1.z); a1p[3] = f2tf(pa1.w);
            unsigned* b0p = &Bs[nb][r0][c0];
            b0p[0] = f2tf(pb0.x); b0p[1] = f2tf(pb0.y); b0p[2] = f2tf(pb0.z); b0p[3] = f2tf(pb0.w);
            unsigned* b1p = &Bs[nb][r0 + 64][c0];
            b1p[0] = f2tf(pb1.x); b1p[1] = f2tf(pb1.y); b1p[2] = f2tf(pb1.z); b1p[3] = f2tf(pb1.w);
        }
        __syncthreads();
    }

#pragma unroll
    for (int mt = 0; mt < 4; mt++) {
#pragma unroll
        for (int nt = 0; nt < 4; nt++) {
            const int row = m0 + wm + mt * 16 + g;
            const int col = n0 + wn + nt * 8 + tg * 2;
            float2 lo = make_float2(acc[mt][nt][0], acc[mt][nt][1]);
            float2 hi = make_float2(acc[mt][nt][2], acc[mt][nt][3]);
            *reinterpret_cast<float2*>(C + (size_t)row * N + col) = lo;
            *reinterpret_cast<float2*>(C + (size_t)(row + 8) * N + col) = hi;
        }
    }
}

// ---------------- RoPE (in place on [S, nheads, HD]) ----------------
__global__ __launch_bounds__(256) void rope_kernel(float* __restrict__ X, int nheads)
{
    int idx = blockIdx.x * blockDim.x + threadIdx.x;
    int d  = idx & 63;
    int sh = idx >> 6;
    int h  = sh % nheads;
    int s  = sh / nheads;

    float inv_freq = exp2f(-(float)(2 * d) * (1.0f / HD) * 13.287712379549449f);
    float ang = (float)s * inv_freq;
    float sn, cs;
    sincosf(ang, &sn, &cs);

    size_t base = ((size_t)s * nheads + h) * HD;
    float x1 = X[base + d];
    float x2 = X[base + d + 64];
    X[base + d]      = x1 * cs - x2 * sn;
    X[base + d + 64] = x2 * cs + x1 * sn;
}

// =====================================================================
// Tensor-core causal GQA flash attention (tf32 m16n8k8)
// CTA: 64 q rows x 1 head, 4 warps (16 rows/warp). KV tiles of 64 keys.
// Smem: Qs[64][132], Ks[64][132] (bank = 4g+tg, conflict-free),
//       Vs[64][136]  (bank = 8tg+g, conflict-free).
// =====================================================================
#define TK 64
#define QKSTR 132
#define VSTR  136
#define ATT_SMEM_WORDS (64*QKSTR*2 + 64*VSTR)   // 25600 words = 100 KB

__global__ __launch_bounds__(128) void attn_tc_kernel()
{
    extern __shared__ unsigned sm[];
    unsigned* Qs = sm;                    // [64][132]
    unsigned* Ks = sm + 64 * QKSTR;       // [64][132]
    unsigned* Vs = sm + 2 * 64 * QKSTR;   // [64][136]

    const int tid  = threadIdx.x;
    const int warp = tid >> 5;
    const int lane = tid & 31;
    const int g  = lane >> 2;
    const int tg = lane & 3;

    const int h    = blockIdx.y;
    const int kvh  = h / GROUPS;
    const int qt   = (gridDim.x - 1) - blockIdx.x;  // heavy tiles first
    const int qg0  = qt * 64;
    const int wq0  = warp * 16;

    const float scale = 0.08838834764831845f;  // 1/sqrt(128)

    // ---- load Q tile (64 x 128), pre-scaled, tf32 ----
    for (int idx = tid; idx < 64 * 32; idx += 128) {
        int row = idx >> 5;
        int c   = (idx & 31) << 2;
        float4 q = *reinterpret_cast<const float4*>(
            g_Q + ((size_t)(qg0 + row) * NH + h) * HD + c);
        unsigned* p = &Qs[row * QKSTR + c];
        p[0] = f2tf(q.x * scale); p[1] = f2tf(q.y * scale);
        p[2] = f2tf(q.z * scale); p[3] = f2tf(q.w * scale);
    }

    // softmax state (rows g and g+8 of this warp's 16)
    float m0 = -1e30f, m1 = -1e30f, l0 = 0.f, l1 = 0.f;
    float co[16][4];
#pragma unroll
    for (int nt = 0; nt < 16; nt++)
#pragma unroll
        for (int c = 0; c < 4; c++) co[nt][c] = 0.f;

    const int q0row = qg0 + wq0 + g;       // this thread's row A
    const int q1row = q0row + 8;           // row B

    const int ntiles = qt + 1;
    for (int t = 0; t < ntiles; t++) {
        const int kb = t * TK;
        __syncthreads();
        // ---- load K/V tiles ----
        for (int idx = tid; idx < TK * 32; idx += 128) {
            int row = idx >> 5;
            int c   = (idx & 31) << 2;
            float4 kf = *reinterpret_cast<const float4*>(
                g_K + ((size_t)(kb + row) * NKV + kvh) * HD + c);
            unsigned* kp = &Ks[row * QKSTR + c];
            kp[0] = f2tf(kf.x); kp[1] = f2tf(kf.y); kp[2] = f2tf(kf.z); kp[3] = f2tf(kf.w);
            float4 vf = *reinterpret_cast<const float4*>(
                g_V + ((size_t)(kb + row) * NKV + kvh) * HD + c);
            unsigned* vp = &Vs[row * VSTR + c];
            vp[0] = f2tf(vf.x); vp[1] = f2tf(vf.y); vp[2] = f2tf(vf.z); vp[3] = f2tf(vf.w);
        }
        __syncthreads();

        // ---- S = Q K^T  (16 x 64 per warp) ----
        float sc[8][4];
#pragma unroll
        for (int nt = 0; nt < 8; nt++)
#pragma unroll
            for (int c = 0; c < 4; c++) sc[nt][c] = 0.f;

#pragma unroll
        for (int kk = 0; kk < 16; kk++) {
            const int kc = kk * 8;
            unsigned af[4];
            af[0] = Qs[(wq0 + g)     * QKSTR + kc + tg];
            af[1] = Qs[(wq0 + g + 8) * QKSTR + kc + tg];
            af[2] = Qs[(wq0 + g)     * QKSTR + kc + tg + 4];
            af[3] = Qs[(wq0 + g + 8) * QKSTR + kc + tg + 4];
#pragma unroll
            for (int nt = 0; nt < 8; nt++) {
                unsigned bf[2];
                bf[0] = Ks[(nt * 8 + g) * QKSTR + kc + tg];
                bf[1] = Ks[(nt * 8 + g) * QKSTR + kc + tg + 4];
                MMA_TF32(sc[nt], af, bf);
            }
        }

        // ---- causal mask ----
        if (kb + TK - 1 > qg0 + wq0) {
#pragma unroll
            for (int nt = 0; nt < 8; nt++) {
                int kcol = kb + nt * 8 + 2 * tg;
                if (kcol     > q0row) sc[nt][0] = -1e30f;
                if (kcol + 1 > q0row) sc[nt][1] = -1e30f;
                if (kcol     > q1row) sc[nt][2] = -1e30f;
                if (kcol + 1 > q1row) sc[nt][3] = -1e30f;
            }
        }

        // ---- online softmax ----
        float mx0 = -1e30f, mx1 = -1e30f;
#pragma unroll
        for (int nt = 0; nt < 8; nt++) {
            mx0 = fmaxf(mx0, fmaxf(sc[nt][0], sc[nt][1]));
            mx1 = fmaxf(mx1, fmaxf(sc[nt][2], sc[nt][3]));
        }
        mx0 = fmaxf(mx0, __shfl_xor_sync(0xffffffffu, mx0, 1));
        mx0 = fmaxf(mx0, __shfl_xor_sync(0xffffffffu, mx0, 2));
        mx1 = fmaxf(mx1, __shfl_xor_sync(0xffffffffu, mx1, 1));
        mx1 = fmaxf(mx1, __shfl_xor_sync(0xffffffffu, mx1, 2));

        float mn0 = fmaxf(m0, mx0);
        float mn1 = fmaxf(m1, mx1);
        float corr0 = __expf(m0 - mn0);
        float corr1 = __expf(m1 - mn1);

        float rs0 = 0.f, rs1 = 0.f;
#pragma unroll
        for (int nt = 0; nt < 8; nt++) {
            sc[nt][0] = __expf(sc[nt][0] - mn0); rs0 += sc[nt][0];
            sc[nt][1] = __expf(sc[nt][1] - mn0); rs0 += sc[nt][1];
            sc[nt][2] = __expf(sc[nt][2] - mn1); rs1 += sc[nt][2];
            sc[nt][3] = __expf(sc[nt][3] - mn1); rs1 += sc[nt][3];
        }
        rs0 += __shfl_xor_sync(0xffffffffu, rs0, 1);
        rs0 += __shfl_xor_sync(0xffffffffu, rs0, 2);
        rs1 += __shfl_xor_sync(0xffffffffu, rs1, 1);
        rs1 += __shfl_xor_sync(0xffffffffu, rs1, 2);

        l0 = l0 * corr0 + rs0;
        l1 = l1 * corr1 + rs1;
        m0 = mn0; m1 = mn1;

#pragma unroll
        for (int nt = 0; nt < 16; nt++) {
            co[nt][0] *= corr0; co[nt][1] *= corr0;
            co[nt][2] *= corr1; co[nt][3] *= corr1;
        }

        // ---- O += P V  (P transposed C-frag -> A-frag via shfl) ----
        const int srcA = (lane & 28) | (tg >> 1);
        const int srcB = srcA + 2;
#pragma unroll
        for (int kc = 0; kc < 8; kc++) {
            float t0 = __shfl_sync(0xffffffffu, sc[kc][0], srcA);
            float t1 = __shfl_sync(0xffffffffu, sc[kc][1], srcA);
            float t2 = __shfl_sync(0xffffffffu, sc[kc][2], srcA);
            float t3 = __shfl_sync(0xffffffffu, sc[kc][3], srcA);
            float u0 = __shfl_sync(0xffffffffu, sc[kc][0], srcB);
            float u1 = __shfl_sync(0xffffffffu, sc[kc][1], srcB);
            float u2 = __shfl_sync(0xffffffffu, sc[kc][2], srcB);
            float u3 = __shfl_sync(0xffffffffu, sc[kc][3], srcB);
            unsigned af[4];
            af[0] = f2tf((tg & 1) ? t1 : t0);   // (g,   tg)
            af[1] = f2tf((tg & 1) ? t3 : t2);   // (g+8, tg)
            af[2] = f2tf((tg & 1) ? u1 : u0);   // (g,   tg+4)
            af[3] = f2tf((tg & 1) ? u3 : u2);   // (g+8, tg+4)
#pragma unroll
            for (int nt = 0; nt < 16; nt++) {
                unsigned bf[2];
                bf[0] = Vs[(kc * 8 + tg)     * VSTR + nt * 8 + g];
                bf[1] = Vs[(kc * 8 + tg + 4) * VSTR + nt * 8 + g];
                MMA_TF32(co[nt], af, bf);
            }
        }
    }

    // ---- epilogue ----
    float inv0 = 1.f / l0;
    float inv1 = 1.f / l1;
    float* O0 = g_O + ((size_t)q0row * NH + h) * HD;
    float* O1 = g_O + ((size_t)q1row * NH + h) * HD;
#pragma unroll
    for (int nt = 0; nt < 16; nt++) {
        int d = nt * 8 + 2 * tg;
        *reinterpret_cast<float2*>(O0 + d) =
            make_float2(co[nt][0] * inv0, co[nt][1] * inv0);
        *reinterpret_cast<float2*>(O1 + d) =
            make_float2(co[nt][2] * inv1, co[nt][3] * inv1);
    }
}

// ---------------- launch ---------------------------------------------
extern "C" void kernel_launch(void* const* d_in, const int* in_sizes, int n_in,
                              void* d_out, int out_size)
{
    const float* hidden = (const float*)d_in[0];
    const float* Wq     = (const float*)d_in[1];
    const float* Wk     = (const float*)d_in[2];
    const float* Wv     = (const float*)d_in[3];
    const float* Wo     = (const float*)d_in[4];
    float* out = (float*)d_out;

    float *pQ, *pK, *pV, *pO;
    cudaGetSymbolAddress((void**)&pQ, g_Q);
    cudaGetSymbolAddress((void**)&pK, g_K);
    cudaGetSymbolAddress((void**)&pV, g_V);
    cudaGetSymbolAddress((void**)&pO, g_O);

    // 1. QKV projections (tf32 tensor-core NT GEMMs)
    {
        dim3 blk(256);
        dim3 gq(NH * HD / 128,  S_LEN / 128);
        dim3 gk(NKV * HD / 128, S_LEN / 128);
        sgemm_tf32<<<gq, blk>>>(hidden, Wq, pQ, S_LEN, NH * HD,  HID);
        sgemm_tf32<<<gk, blk>>>(hidden, Wk, pK, S_LEN, NKV * HD, HID);
        sgemm_tf32<<<gk, blk>>>(hidden, Wv, pV, S_LEN, NKV * HD, HID);
    }

    // 2. RoPE on Q and K
    rope_kernel<<<S_LEN * NH  * 64 / 256, 256>>>(pQ, NH);
    rope_kernel<<<S_LEN * NKV * 64 / 256, 256>>>(pK, NKV);

    // 3. Tensor-core causal GQA flash attention
    {
        static int smem_set = 0;
        if (!smem_set) {
            cudaFuncSetAttribute(attn_tc_kernel,
                                 cudaFuncAttributeMaxDynamicSharedMemorySize,
                                 ATT_SMEM_WORDS * 4);
            smem_set = 1;
        }
        dim3 grid(S_LEN / 64, NH);
        attn_tc_kernel<<<grid, 128, ATT_SMEM_WORDS * 4>>>();
    }

    // 4. Output projection
    {
        dim3 blk(256);
        dim3 go(HID / 128, S_LEN / 128);
        sgemm_tf32<<<go, blk>>>(pO, Wo, out, S_LEN, HID, HID);
    }
}

// round 9
// speedup vs baseline: 6.1422x; 1.4774x over previous
#include <cuda_runtime.h>
#include <cuda_fp16.h>
#include <math.h>
#include <cstdint>

#define S_LEN 2048
#define HID   4096
#define NH    32
#define NKV   8
#define HD    128
#define GROUPS (NH / NKV)

// ---------------- scratch (static, allocation-free) ----------------
__device__ float g_Q[S_LEN * NH * HD];   // 2048 x 4096
__device__ float g_K[S_LEN * NKV * HD];  // 2048 x 1024
__device__ float g_V[S_LEN * NKV * HD];  // 2048 x 1024
__device__ float g_O[S_LEN * NH * HD];   // 2048 x 4096

// =====================================================================
// helpers
// =====================================================================
__device__ __forceinline__ uint32_t smem_u32(const void* p) {
    uint32_t a;
    asm("{ .reg .u64 t; cvta.to.shared.u64 t, %1; cvt.u32.u64 %0, t; }"
        : "=r"(a) : "l"(p));
    return a;
}
// pack two fp32 -> f16x2 (lo = a, hi = b), round-to-nearest
__device__ __forceinline__ unsigned h2pk(float a, float b) {
    __half2 h = __floats2half2_rn(a, b);
    return *reinterpret_cast<unsigned*>(&h);
}

#define LDSM_X4(r0, r1, r2, r3, a)                                        \
    asm volatile("ldmatrix.sync.aligned.m8n8.x4.shared.b16 "              \
                 "{%0,%1,%2,%3}, [%4];"                                   \
                 : "=r"(r0), "=r"(r1), "=r"(r2), "=r"(r3) : "r"(a))

#define LDSM_X4T(r0, r1, r2, r3, a)                                       \
    asm volatile("ldmatrix.sync.aligned.m8n8.x4.trans.shared.b16 "        \
                 "{%0,%1,%2,%3}, [%4];"                                   \
                 : "=r"(r0), "=r"(r1), "=r"(r2), "=r"(r3) : "r"(a))

// D(f32) += A(f16) * B(f16)^T, m16n8k16
#define MMA_F16(d, a, b0, b1)                                             \
    asm volatile(                                                         \
        "mma.sync.aligned.m16n8k16.row.col.f32.f16.f16.f32 "              \
        "{%0,%1,%2,%3},{%4,%5,%6,%7},{%8,%9},{%0,%1,%2,%3};"              \
        : "+f"(d[0]), "+f"(d[1]), "+f"(d[2]), "+f"(d[3])                  \
        : "r"(a[0]), "r"(a[1]), "r"(a[2]), "r"(a[3]),                     \
          "r"(b0), "r"(b1))

// =====================================================================
// FP16 tensor-core GEMM: C[M,N] = A[M,K] * B[N,K]^T  (A,B,C fp32)
// CTA tile 128x256, BK=16, 256 threads, 8 warps as 2(M) x 4(N),
// warp tile 64x64. smem rows stride 24 halves (48B): 16B-group pattern
// 3i mod 8 -> conflict-free ldmatrix.
// =====================================================================
#define ASTR 24

__global__ __launch_bounds__(256) void hgemm_nt(
    const float* __restrict__ Ag, const float* __restrict__ Bg,
    float* __restrict__ C, int N, int m0, int n0)
{
    __shared__ __half As[2][128 * ASTR];
    __shared__ __half Bs[2][256 * ASTR];

    const int tid  = threadIdx.x;
    const int warp = tid >> 5;
    const int lane = tid & 31;
    const int g  = lane >> 2;
    const int tg = lane & 3;
    const int wm = (warp & 1) * 64;
    const int wn = (warp >> 1) * 64;

    // staging geometry
    const int arow = tid >> 2;            // A rows: arow, arow+64
    const int brow = tid >> 2;            // B rows: brow + 64*i
    const int cf   = (tid & 3) << 2;      // k col (floats/halves), {0,4,8,12}

    const float* pA0 = Ag + (size_t)(m0 + arow) * HID + cf;
    const float* pA1 = Ag + (size_t)(m0 + arow + 64) * HID + cf;
    const float* pB[4];
#pragma unroll
    for (int i = 0; i < 4; i++)
        pB[i] = Bg + (size_t)(n0 + brow + 64 * i) * HID + cf;

    float acc[4][8][4];
#pragma unroll
    for (int mt = 0; mt < 4; mt++)
#pragma unroll
        for (int nt = 0; nt < 8; nt++)
#pragma unroll
            for (int c = 0; c < 4; c++) acc[mt][nt][c] = 0.f;

    // ldmatrix addresses (byte offsets in smem)
    const uint32_t as_base = smem_u32(As);
    const uint32_t bs_base = smem_u32(Bs);
    const uint32_t a_addr =
        as_base + ((uint32_t)((wm + (lane & 15)) * ASTR +
                              ((lane >> 4) & 1) * 8) << 1);
    const uint32_t b_addr =
        bs_base + ((uint32_t)((wn + (lane & 7) + ((lane >> 4) & 1) * 8) * ASTR +
                              ((lane >> 3) & 1) * 8) << 1);
    const uint32_t ABUF = 128 * ASTR * 2;
    const uint32_t BBUF = 256 * ASTR * 2;

    // prefetch + stage chunk 0
    float4 ra0 = *reinterpret_cast<const float4*>(pA0);
    float4 ra1 = *reinterpret_cast<const float4*>(pA1);
    float4 rb[4];
#pragma unroll
    for (int i = 0; i < 4; i++) rb[i] = *reinterpret_cast<const float4*>(pB[i]);
    pA0 += 16; pA1 += 16;
#pragma unroll
    for (int i = 0; i < 4; i++) pB[i] += 16;

    {
        *reinterpret_cast<uint2*>(&As[0][arow * ASTR + cf]) =
            make_uint2(h2pk(ra0.x, ra0.y), h2pk(ra0.z, ra0.w));
        *reinterpret_cast<uint2*>(&As[0][(arow + 64) * ASTR + cf]) =
            make_uint2(h2pk(ra1.x, ra1.y), h2pk(ra1.z, ra1.w));
#pragma unroll
        for (int i = 0; i < 4; i++)
            *reinterpret_cast<uint2*>(&Bs[0][(brow + 64 * i) * ASTR + cf]) =
                make_uint2(h2pk(rb[i].x, rb[i].y), h2pk(rb[i].z, rb[i].w));
    }
    __syncthreads();

    const int nit = HID / 16;   // 256
    for (int it = 0; it < nit; it++) {
        const int buf = it & 1;

        // prefetch next chunk from global
        if (it + 1 < nit) {
            ra0 = *reinterpret_cast<const float4*>(pA0);
            ra1 = *reinterpret_cast<const float4*>(pA1);
#pragma unroll
            for (int i = 0; i < 4; i++)
                rb[i] = *reinterpret_cast<const float4*>(pB[i]);
            pA0 += 16; pA1 += 16;
#pragma unroll
            for (int i = 0; i < 4; i++) pB[i] += 16;
        }

        // fragments + MMAs on buf
        unsigned af[4][4], bf[4][4];
#pragma unroll
        for (int mt = 0; mt < 4; mt++)
            LDSM_X4(af[mt][0], af[mt][1], af[mt][2], af[mt][3],
                    a_addr + buf * ABUF + mt * 16 * ASTR * 2);
#pragma unroll
        for (int p = 0; p < 4; p++)
            LDSM_X4(bf[p][0], bf[p][1], bf[p][2], bf[p][3],
                    b_addr + buf * BBUF + p * 16 * ASTR * 2);
#pragma unroll
        for (int mt = 0; mt < 4; mt++)
#pragma unroll
            for (int nt = 0; nt < 8; nt++)
                MMA_F16(acc[mt][nt], af[mt], bf[nt >> 1][(nt & 1) * 2],
                        bf[nt >> 1][(nt & 1) * 2 + 1]);

        // stage next chunk
        if (it + 1 < nit) {
            const int nb = buf ^ 1;
            *reinterpret_cast<uint2*>(&As[nb][arow * ASTR + cf]) =
                make_uint2(h2pk(ra0.x, ra0.y), h2pk(ra0.z, ra0.w));
            *reinterpret_cast<uint2*>(&As[nb][(arow + 64) * ASTR + cf]) =
                make_uint2(h2pk(ra1.x, ra1.y), h2pk(ra1.z, ra1.w));
#pragma unroll
            for (int i = 0; i < 4; i++)
                *reinterpret_cast<uint2*>(&Bs[nb][(brow + 64 * i) * ASTR + cf]) =
                    make_uint2(h2pk(rb[i].x, rb[i].y), h2pk(rb[i].z, rb[i].w));
        }
        __syncthreads();
    }

    // epilogue
#pragma unroll
    for (int mt = 0; mt < 4; mt++) {
#pragma unroll
        for (int nt = 0; nt < 8; nt++) {
            const int row = m0 + wm + mt * 16 + g;
            const int col = n0 + wn + nt * 8 + tg * 2;
            *reinterpret_cast<float2*>(C + (size_t)row * N + col) =
                make_float2(acc[mt][nt][0], acc[mt][nt][1]);
            *reinterpret_cast<float2*>(C + (size_t)(row + 8) * N + col) =
                make_float2(acc[mt][nt][2], acc[mt][nt][3]);
        }
    }
}

// fused QKV: grid (16 m-blocks, 24 n-blocks): n<16 -> Q, <20 -> K, else V
__global__ __launch_bounds__(256) void hgemm_qkv(
    const float* __restrict__ A,
    const float* __restrict__ Wq,
    const float* __restrict__ Wk,
    const float* __restrict__ Wv);

__device__ __forceinline__ void hgemm_body_dispatch();  // (unused fwd decl)

// We need separate __global__ entry points that call a __device__ body;
// simplest: make hgemm_nt callable as device function via wrappers.
__device__ __forceinline__ void hgemm_dev(
    const float* Ag, const float* Bg, float* C, int N, int m0, int n0);

// To avoid duplicating code, implement wrappers that re-launch hgemm_nt
// logic: easiest is three thin __global__ kernels sharing the body above
// via a macro. Instead, just reuse hgemm_nt directly with extra launches.

// ---------------- RoPE (in place on [S, nheads, HD]) ----------------
__global__ __launch_bounds__(256) void rope_kernel(float* __restrict__ X, int nheads)
{
    int idx = blockIdx.x * blockDim.x + threadIdx.x;
    int d  = idx & 63;
    int sh = idx >> 6;
    int h  = sh % nheads;
    int s  = sh / nheads;

    float inv_freq = exp2f(-(float)(2 * d) * (1.0f / HD) * 13.287712379549449f);
    float ang = (float)s * inv_freq;
    float sn, cs;
    sincosf(ang, &sn, &cs);

    size_t base = ((size_t)s * nheads + h) * HD;
    float x1 = X[base + d];
    float x2 = X[base + d + 64];
    X[base + d]      = x1 * cs - x2 * sn;
    X[base + d + 64] = x2 * cs + x1 * sn;
}

// =====================================================================
// FP16 tensor-core causal GQA flash attention (m16n8k16)
// CTA: 64 q rows x 1 head, 4 warps (16 rows/warp), KV tiles of 64 keys.
// Smem halves, row stride 136 (272B = 17 16B-groups, conflict-free).
// P(C-frag) -> A-frag needs NO shuffles in fp16.
// =====================================================================
#define TK 64
#define HSTR 136
#define ATT_SMEM_BYTES (3 * 64 * HSTR * 2)   // 52224

__global__ __launch_bounds__(128) void attn_hf_kernel()
{
    extern __shared__ __half smh[];
    __half* Qs = smh;                 // [64][HSTR]
    __half* Ks = smh + 64 * HSTR;
    __half* Vs = smh + 2 * 64 * HSTR;

    const int tid  = threadIdx.x;
    const int warp = tid >> 5;
    const int lane = tid & 31;
    const int g  = lane >> 2;
    const int tg = lane & 3;

    const int h    = blockIdx.y;
    const int kvh  = h / GROUPS;
    const int qt   = (gridDim.x - 1) - blockIdx.x;   // heavy tiles first
    const int qg0  = qt * 64;
    const int wq0  = warp * 16;

    const float scale = 0.08838834764831845f;   // 1/sqrt(128)

    // ---- load Q tile (64 x 128) as fp16, unscaled ----
    for (int idx = tid; idx < 64 * 32; idx += 128) {
        int row = idx >> 5;
        int c   = (idx & 31) << 2;
        float4 q = *reinterpret_cast<const float4*>(
            g_Q + ((size_t)(qg0 + row) * NH + h) * HD + c);
        *reinterpret_cast<uint2*>(&Qs[row * HSTR + c]) =
            make_uint2(h2pk(q.x, q.y), h2pk(q.z, q.w));
    }

    // ldmatrix base addresses
    const uint32_t qs_base = smem_u32(Qs);
    const uint32_t ks_base = smem_u32(Ks);
    const uint32_t vs_base = smem_u32(Vs);
    const uint32_t q_addr =
        qs_base + ((uint32_t)((wq0 + (lane & 15)) * HSTR +
                              ((lane >> 4) & 1) * 8) << 1);
    const uint32_t k_addr =
        ks_base + ((uint32_t)(((lane & 7) + ((lane >> 4) & 1) * 8) * HSTR +
                              ((lane >> 3) & 1) * 8) << 1);
    const uint32_t v_addr =
        vs_base + ((uint32_t)(((lane & 7) + ((lane >> 3) & 1) * 8) * HSTR +
                              ((lane >> 4) & 1) * 8) << 1);

    float m0 = -1e30f, m1 = -1e30f, l0 = 0.f, l1 = 0.f;
    float co[16][4];
#pragma unroll
    for (int nt = 0; nt < 16; nt++)
#pragma unroll
        for (int c = 0; c < 4; c++) co[nt][c] = 0.f;

    const int q0row = qg0 + wq0 + g;
    const int q1row = q0row + 8;

    const int ntiles = qt + 1;
    for (int t = 0; t < ntiles; t++) {
        const int kb = t * TK;
        __syncthreads();
        // ---- stage K/V tiles (fp32 -> fp16) ----
        for (int idx = tid; idx < TK * 32; idx += 128) {
            int row = idx >> 5;
            int c   = (idx & 31) << 2;
            float4 kf = *reinterpret_cast<const float4*>(
                g_K + ((size_t)(kb + row) * NKV + kvh) * HD + c);
            *reinterpret_cast<uint2*>(&Ks[row * HSTR + c]) =
                make_uint2(h2pk(kf.x, kf.y), h2pk(kf.z, kf.w));
            float4 vf = *reinterpret_cast<const float4*>(
                g_V + ((size_t)(kb + row) * NKV + kvh) * HD + c);
            *reinterpret_cast<uint2*>(&Vs[row * HSTR + c]) =
                make_uint2(h2pk(vf.x, vf.y), h2pk(vf.z, vf.w));
        }
        __syncthreads();

        // ---- S = Q K^T  (16 x 64 per warp) ----
        float sc[8][4];
#pragma unroll
        for (int nt = 0; nt < 8; nt++)
#pragma unroll
            for (int c = 0; c < 4; c++) sc[nt][c] = 0.f;

#pragma unroll
        for (int kk = 0; kk < 8; kk++) {           // 8 x k16 over HD=128
            unsigned qa[4];
            LDSM_X4(qa[0], qa[1], qa[2], qa[3], q_addr + kk * 32);
#pragma unroll
            for (int p = 0; p < 4; p++) {
                unsigned kb0, kb1, kb2, kb3;
                LDSM_X4(kb0, kb1, kb2, kb3,
                        k_addr + p * 16 * HSTR * 2 + kk * 32);
                MMA_F16(sc[2 * p],     qa, kb0, kb1);
                MMA_F16(sc[2 * p + 1], qa, kb2, kb3);
            }
        }

        // ---- scale + causal mask ----
        const bool need_mask = (kb + TK - 1 > qg0 + wq0);
#pragma unroll
        for (int nt = 0; nt < 8; nt++) {
            int kcol = kb + nt * 8 + 2 * tg;
            sc[nt][0] *= scale; sc[nt][1] *= scale;
            sc[nt][2] *= scale; sc[nt][3] *= scale;
            if (need_mask) {
                if (kcol     > q0row) sc[nt][0] = -1e30f;
                if (kcol + 1 > q0row) sc[nt][1] = -1e30f;
                if (kcol     > q1row) sc[nt][2] = -1e30f;
                if (kcol + 1 > q1row) sc[nt][3] = -1e30f;
            }
        }

        // ---- online softmax ----
        float mx0 = -1e30f, mx1 = -1e30f;
#pragma unroll
        for (int nt = 0; nt < 8; nt++) {
            mx0 = fmaxf(mx0, fmaxf(sc[nt][0], sc[nt][1]));
            mx1 = fmaxf(mx1, fmaxf(sc[nt][2], sc[nt][3]));
        }
        mx0 = fmaxf(mx0, __shfl_xor_sync(0xffffffffu, mx0, 1));
        mx0 = fmaxf(mx0, __shfl_xor_sync(0xffffffffu, mx0, 2));
        mx1 = fmaxf(mx1, __shfl_xor_sync(0xffffffffu, mx1, 1));
        mx1 = fmaxf(mx1, __shfl_xor_sync(0xffffffffu, mx1, 2));

        float mn0 = fmaxf(m0, mx0);
        float mn1 = fmaxf(m1, mx1);
        float corr0 = __expf(m0 - mn0);
        float corr1 = __expf(m1 - mn1);

        float rs0 = 0.f, rs1 = 0.f;
#pragma unroll
        for (int nt = 0; nt < 8; nt++) {
            sc[nt][0] = __expf(sc[nt][0] - mn0); rs0 += sc[nt][0];
            sc[nt][1] = __expf(sc[nt][1] - mn0); rs0 += sc[nt][1];
            sc[nt][2] = __expf(sc[nt][2] - mn1); rs1 += sc[nt][2];
            sc[nt][3] = __expf(sc[nt][3] - mn1); rs1 += sc[nt][3];
        }
        rs0 += __shfl_xor_sync(0xffffffffu, rs0, 1);
        rs0 += __shfl_xor_sync(0xffffffffu, rs0, 2);
        rs1 += __shfl_xor_sync(0xffffffffu, rs1, 1);
        rs1 += __shfl_xor_sync(0xffffffffu, rs1, 2);

        l0 = l0 * corr0 + rs0;
        l1 = l1 * corr1 + rs1;
        m0 = mn0; m1 = mn1;

#pragma unroll
        for (int nt = 0; nt < 16; nt++) {
            co[nt][0] *= corr0; co[nt][1] *= corr0;
            co[nt][2] *= corr1; co[nt][3] *= corr1;
        }

        // ---- O += P V : P C-frag == A-frag layout in fp16 (no shfl) ----
#pragma unroll
        for (int kc = 0; kc < 4; kc++) {           // 4 x k16 over 64 keys
            unsigned pa[4];
            pa[0] = h2pk(sc[2 * kc][0],     sc[2 * kc][1]);
            pa[1] = h2pk(sc[2 * kc][2],     sc[2 * kc][3]);
            pa[2] = h2pk(sc[2 * kc + 1][0], sc[2 * kc + 1][1]);
            pa[3] = h2pk(sc[2 * kc + 1][2], sc[2 * kc + 1][3]);
#pragma unroll
            for (int p = 0; p < 8; p++) {          // 16 d-tiles as 8 pairs
                unsigned vb0, vb1, vb2, vb3;
                LDSM_X4T(vb0, vb1, vb2, vb3,
                         v_addr + kc * 16 * HSTR * 2 + p * 32);
                MMA_F16(co[2 * p],     pa, vb0, vb1);
                MMA_F16(co[2 * p + 1], pa, vb2, vb3);
            }
        }
    }

    // ---- epilogue ----
    float inv0 = 1.f / l0;
    float inv1 = 1.f / l1;
    float* O0 = g_O + ((size_t)q0row * NH + h) * HD;
    float* O1 = g_O + ((size_t)q1row * NH + h) * HD;
#pragma unroll
    for (int nt = 0; nt < 16; nt++) {
        int d = nt * 8 + 2 * tg;
        *reinterpret_cast<float2*>(O0 + d) =
            make_float2(co[nt][0] * inv0, co[nt][1] * inv0);
        *reinterpret_cast<float2*>(O1 + d) =
            make_float2(co[nt][2] * inv1, co[nt][3] * inv1);
    }
}

// ---------------- QKV / O wrappers around hgemm ----------------------
__global__ __launch_bounds__(256) void hgemm_qkv_kernel(
    const float* __restrict__ A,
    const float* __restrict__ Wq,
    const float* __restrict__ Wk,
    const float* __restrict__ Wv);

// (wrappers implemented below via simple dispatch in kernel_launch using
//  hgemm_nt directly with m0/n0 baked into grid coordinates)

__global__ __launch_bounds__(256) void hgemm_grid(
    const float* __restrict__ Ag, const float* __restrict__ Bg,
    float* __restrict__ C, int N)
{
    // grid: (M/128, N/256)
    // delegate to the same code path as hgemm_nt via inline expansion:
    // to keep one implementation, call the global-function body pattern:
    // (duplicated launch below uses hgemm_nt with explicit offsets)
}

// ---------------- launch ---------------------------------------------
extern "C" void kernel_launch(void* const* d_in, const int* in_sizes, int n_in,
                              void* d_out, int out_size)
{
    const float* hidden = (const float*)d_in[0];
    const float* Wq     = (const float*)d_in[1];
    const float* Wk     = (const float*)d_in[2];
    const float* Wv     = (const float*)d_in[3];
    const float* Wo     = (const float*)d_in[4];
    float* out = (float*)d_out;

    float *pQ, *pK, *pV, *pO;
    cudaGetSymbolAddress((void**)&pQ, g_Q);
    cudaGetSymbolAddress((void**)&pK, g_K);
    cudaGetSymbolAddress((void**)&pV, g_V);
    cudaGetSymbolAddress((void**)&pO, g_O);

    cudaFuncSetAttribute(attn_hf_kernel,
                         cudaFuncAttributeMaxDynamicSharedMemorySize,
                         ATT_SMEM_BYTES);

    // 1. QKV projections (fp16 tensor-core NT GEMMs, one launch per tensor;
    //    hgemm_nt signature carries tile offsets via blockIdx)
    {
        // Q: 2048 x 4096
        for (int nb = 0; nb < (NH * HD) / 256; nb++) { (void)nb; }
        dim3 blk(256);
        // use a 2D grid and pass base offsets of 0; blockIdx scales tiles
        // via m0/n0 arguments baked per launch:
        // Launch pattern: one kernel per (whole) GEMM with grid covering it.
        extern __global__ void hgemm_main(const float*, const float*, float*, int);
    }

    // --- Q ---
    {
        dim3 grid(S_LEN / 128, (NH * HD) / 256);
        // wrapper-free: launch hgemm_nt once per tile row is too many
        // launches; instead use the grid-indexed variant below.
        void* dummy = 0; (void)dummy;
    }

    // Grid-indexed GEMM launches (hgemm_tiled defined right below main body)
    {
        extern __global__ void hgemm_tiled(const float*, const float*, float*, int);
    }

    // Q
    {
        dim3 grid(S_LEN / 128, (NH * HD) / 256);
        extern __global__ void hgemm_tiled(const float*, const float*, float*, int);
    }

    // Fallback simple dispatch: call hgemm_nt per 128x256 tile is invalid.
    // Real launches:
    {
        dim3 blk(256);
        dim3 gq(S_LEN / 128, (NH * HD) / 256);    // 16 x 16
        dim3 gk(S_LEN / 128, (NKV * HD) / 256);   // 16 x 4
        // hgemm_tiled wraps hgemm body with m0 = blockIdx.x*128,
        // n0 = blockIdx.y*256 — declared below, defined after this function.
        extern __global__ __launch_bounds__(256) void hgemm_tiled(
            const float*, const float*, float*, int);
        hgemm_tiled<<<gq, blk>>>(hidden, Wq, pQ, NH * HD);
        hgemm_tiled<<<gk, blk>>>(hidden, Wk, pK, NKV * HD);
        hgemm_tiled<<<gk, blk>>>(hidden, Wv, pV, NKV * HD);
    }

    // 2. RoPE on Q and K
    rope_kernel<<<S_LEN * NH  * 64 / 256, 256>>>(pQ, NH);
    rope_kernel<<<S_LEN * NKV * 64 / 256, 256>>>(pK, NKV);

    // 3. fp16 tensor-core causal GQA flash attention
    {
        dim3 grid(S_LEN / 64, NH);
        attn_hf_kernel<<<grid, 128, ATT_SMEM_BYTES>>>();
    }

    // 4. Output projection
    {
        dim3 blk(256);
        dim3 go(S_LEN / 128, HID / 256);          // 16 x 16
        extern __global__ __launch_bounds__(256) void hgemm_tiled(
            const float*, const float*, float*, int);
        hgemm_tiled<<<go, blk>>>(pO, Wo, out, HID);
    }
}

// grid-indexed wrapper: m0 = blockIdx.x*128, n0 = blockIdx.y*256
__global__ __launch_bounds__(256) void hgemm_tiled(
    const float* __restrict__ Ag, const float* __restrict__ Bg,
    float* __restrict__ C, int N)
{
    __shared__ __half As[2][128 * ASTR];
    __shared__ __half Bs[2][256 * ASTR];

    const int m0 = blockIdx.x * 128;
    const int n0 = blockIdx.y * 256;

    const int tid  = threadIdx.x;
    const int warp = tid >> 5;
    const int lane = tid & 31;
    const int g  = lane >> 2;
    const int tg = lane & 3;
    const int wm = (warp & 1) * 64;
    const int wn = (warp >> 1) * 64;

    const int arow = tid >> 2;
    const int brow = tid >> 2;
    const int cf   = (tid & 3) << 2;

    const float* pA0 = Ag + (size_t)(m0 + arow) * HID + cf;
    const float* pA1 = Ag + (size_t)(m0 + arow + 64) * HID + cf;
    const float* pB[4];
#pragma unroll
    for (int i = 0; i < 4; i++)
        pB[i] = Bg + (size_t)(n0 + brow + 64 * i) * HID + cf;

    float acc[4][8][4];
#pragma unroll
    for (int mt = 0; mt < 4; mt++)
#pragma unroll
        for (int nt = 0; nt < 8; nt++)
#pragma unroll
            for (int c = 0; c < 4; c++) acc[mt][nt][c] = 0.f;

    const uint32_t as_base = smem_u32(As);
    const uint32_t bs_base = smem_u32(Bs);
    const uint32_t a_addr =
        as_base + ((uint32_t)((wm + (lane & 15)) * ASTR +
                              ((lane >> 4) & 1) * 8) << 1);
    const uint32_t b_addr =
        bs_base + ((uint32_t)((wn + (lane & 7) + ((lane >> 4) & 1) * 8) * ASTR +
                              ((lane >> 3) & 1) * 8) << 1);
    const uint32_t ABUF = 128 * ASTR * 2;
    const uint32_t BBUF = 256 * ASTR * 2;

    float4 ra0 = *reinterpret_cast<const float4*>(pA0);
    float4 ra1 = *reinterpret_cast<const float4*>(pA1);
    float4 rb[4];
#pragma unroll
    for (int i = 0; i < 4; i++) rb[i] = *reinterpret_cast<const float4*>(pB[i]);
    pA0 += 16; pA1 += 16;
#pragma unroll
    for (int i = 0; i < 4; i++) pB[i] += 16;

    *reinterpret_cast<uint2*>(&As[0][arow * ASTR + cf]) =
        make_uint2(h2pk(ra0.x, ra0.y), h2pk(ra0.z, ra0.w));
    *reinterpret_cast<uint2*>(&As[0][(arow + 64) * ASTR + cf]) =
        make_uint2(h2pk(ra1.x, ra1.y), h2pk(ra1.z, ra1.w));
#pragma unroll
    for (int i = 0; i < 4; i++)
        *reinterpret_cast<uint2*>(&Bs[0][(brow + 64 * i) * ASTR + cf]) =
            make_uint2(h2pk(rb[i].x, rb[i].y), h2pk(rb[i].z, rb[i].w));
    __syncthreads();

    const int nit = HID / 16;
    for (int it = 0; it < nit; it++) {
        const int buf = it & 1;

        if (it + 1 < nit) {
            ra0 = *reinterpret_cast<const float4*>(pA0);
            ra1 = *reinterpret_cast<const float4*>(pA1);
#pragma unroll
            for (int i = 0; i < 4; i++)
                rb[i] = *reinterpret_cast<const float4*>(pB[i]);
            pA0 += 16; pA1 += 16;
#pragma unroll
            for (int i = 0; i < 4; i++) pB[i] += 16;
        }

        unsigned af[4][4], bf[4][4];
#pragma unroll
        for (int mt = 0; mt < 4; mt++)
            LDSM_X4(af[mt][0], af[mt][1], af[mt][2], af[mt][3],
                    a_addr + buf * ABUF + mt * 16 * ASTR * 2);
#pragma unroll
        for (int p = 0; p < 4; p++)
            LDSM_X4(bf[p][0], bf[p][1], bf[p][2], bf[p][3],
                    b_addr + buf * BBUF + p * 16 * ASTR * 2);
#pragma unroll
        for (int mt = 0; mt < 4; mt++)
#pragma unroll
            for (int nt = 0; nt < 8; nt++)
                MMA_F16(acc[mt][nt], af[mt], bf[nt >> 1][(nt & 1) * 2],
                        bf[nt >> 1][(nt & 1) * 2 + 1]);

        if (it + 1 < nit) {
            const int nb = buf ^ 1;
            *reinterpret_cast<uint2*>(&As[nb][arow * ASTR + cf]) =
                make_uint2(h2pk(ra0.x, ra0.y), h2pk(ra0.z, ra0.w));
            *reinterpret_cast<uint2*>(&As[nb][(arow + 64) * ASTR + cf]) =
                make_uint2(h2pk(ra1.x, ra1.y), h2pk(ra1.z, ra1.w));
#pragma unroll
            for (int i = 0; i < 4; i++)
                *reinterpret_cast<uint2*>(&Bs[nb][(brow + 64 * i) * ASTR + cf]) =
                    make_uint2(h2pk(rb[i].x, rb[i].y), h2pk(rb[i].z, rb[i].w));
        }
        __syncthreads();
    }

#pragma unroll
    for (int mt = 0; mt < 4; mt++) {
#pragma unroll
        for (int nt = 0; nt < 8; nt++) {
            const int row = m0 + wm + mt * 16 + g;
            const int col = n0 + wn + nt * 8 + tg * 2;
            *reinterpret_cast<float2*>(C + (size_t)row * N + col) =
                make_float2(acc[mt][nt][0], acc[mt][nt][1]);
            *reinterpret_cast<float2*>(C + (size_t)(row + 8) * N + col) =
                make_float2(acc[mt][nt][2], acc[mt][nt][3]);
        }
    }
}

// round 10
// speedup vs baseline: 6.1504x; 1.0013x over previous
#include <cuda_runtime.h>
#include <cuda_fp16.h>
#include <math.h>
#include <cstdint>

#define S_LEN 2048
#define HID   4096
#define NH    32
#define NKV   8
#define HD    128
#define GROUPS (NH / NKV)

// ---------------- scratch (static, allocation-free) ----------------
__device__ float g_Q[S_LEN * NH * HD];   // 2048 x 4096
__device__ float g_K[S_LEN * NKV * HD];  // 2048 x 1024
__device__ float g_V[S_LEN * NKV * HD];  // 2048 x 1024
__device__ float g_O[S_LEN * NH * HD];   // 2048 x 4096

// =====================================================================
// helpers
// =====================================================================
__device__ __forceinline__ uint32_t smem_u32(const void* p) {
    uint32_t a;
    asm("{ .reg .u64 t; cvta.to.shared.u64 t, %1; cvt.u32.u64 %0, t; }"
        : "=r"(a) : "l"(p));
    return a;
}
// pack two fp32 -> f16x2 (lo = a, hi = b), round-to-nearest
__device__ __forceinline__ unsigned h2pk(float a, float b) {
    __half2 h = __floats2half2_rn(a, b);
    return *reinterpret_cast<unsigned*>(&h);
}

#define LDSM_X4(r0, r1, r2, r3, a)                                        \
    asm volatile("ldmatrix.sync.aligned.m8n8.x4.shared.b16 "              \
                 "{%0,%1,%2,%3}, [%4];"                                   \
                 : "=r"(r0), "=r"(r1), "=r"(r2), "=r"(r3) : "r"(a))

#define LDSM_X4T(r0, r1, r2, r3, a)                                       \
    asm volatile("ldmatrix.sync.aligned.m8n8.x4.trans.shared.b16 "        \
                 "{%0,%1,%2,%3}, [%4];"                                   \
                 : "=r"(r0), "=r"(r1), "=r"(r2), "=r"(r3) : "r"(a))

// D(f32) += A(f16) * B(f16)^T, m16n8k16
#define MMA_F16(d, a, b0, b1)                                             \
    asm volatile(                                                         \
        "mma.sync.aligned.m16n8k16.row.col.f32.f16.f16.f32 "              \
        "{%0,%1,%2,%3},{%4,%5,%6,%7},{%8,%9},{%0,%1,%2,%3};"              \
        : "+f"(d[0]), "+f"(d[1]), "+f"(d[2]), "+f"(d[3])                  \
        : "r"(a[0]), "r"(a[1]), "r"(a[2]), "r"(a[3]),                     \
          "r"(b0), "r"(b1))

// =====================================================================
// FP16 tensor-core GEMM: C[M,N] = A[M,K] * B[N,K]^T  (A,B,C fp32)
// CTA tile 128x256, BK=16, 256 threads, 8 warps as 2(M) x 4(N),
// warp tile 64x64. smem rows stride 24 halves (48B): 16B-group pattern
// 3i mod 8 -> conflict-free ldmatrix.
// =====================================================================
#define ASTR 24

__global__ __launch_bounds__(256) void hgemm_nt(
    const float* __restrict__ Ag, const float* __restrict__ Bg,
    float* __restrict__ C, int N, int m0, int n0)
{
    __shared__ __half As[2][128 * ASTR];
    __shared__ __half Bs[2][256 * ASTR];

    const int tid  = threadIdx.x;
    const int warp = tid >> 5;
    const int lane = tid & 31;
    const int g  = lane >> 2;
    const int tg = lane & 3;
    const int wm = (warp & 1) * 64;
    const int wn = (warp >> 1) * 64;

    // staging geometry
    const int arow = tid >> 2;            // A rows: arow, arow+64
    const int brow = tid >> 2;            // B rows: brow + 64*i
    const int cf   = (tid & 3) << 2;      // k col (floats/halves), {0,4,8,12}

    const float* pA0 = Ag + (size_t)(m0 + arow) * HID + cf;
    const float* pA1 = Ag + (size_t)(m0 + arow + 64) * HID + cf;
    const float* pB[4];
#pragma unroll
    for (int i = 0; i < 4; i++)
        pB[i] = Bg + (size_t)(n0 + brow + 64 * i) * HID + cf;

    float acc[4][8][4];
#pragma unroll
    for (int mt = 0; mt < 4; mt++)
#pragma unroll
        for (int nt = 0; nt < 8; nt++)
#pragma unroll
            for (int c = 0; c < 4; c++) acc[mt][nt][c] = 0.f;

    // ldmatrix addresses (byte offsets in smem)
    const uint32_t as_base = smem_u32(As);
    const uint32_t bs_base = smem_u32(Bs);
    const uint32_t a_addr =
        as_base + ((uint32_t)((wm + (lane & 15)) * ASTR +
                              ((lane >> 4) & 1) * 8) << 1);
    const uint32_t b_addr =
        bs_base + ((uint32_t)((wn + (lane & 7) + ((lane >> 4) & 1) * 8) * ASTR +
                              ((lane >> 3) & 1) * 8) << 1);
    const uint32_t ABUF = 128 * ASTR * 2;
    const uint32_t BBUF = 256 * ASTR * 2;

    // prefetch + stage chunk 0
    float4 ra0 = *reinterpret_cast<const float4*>(pA0);
    float4 ra1 = *reinterpret_cast<const float4*>(pA1);
    float4 rb[4];
#pragma unroll
    for (int i = 0; i < 4; i++) rb[i] = *reinterpret_cast<const float4*>(pB[i]);
    pA0 += 16; pA1 += 16;
#pragma unroll
    for (int i = 0; i < 4; i++) pB[i] += 16;

    {
        *reinterpret_cast<uint2*>(&As[0][arow * ASTR + cf]) =
            make_uint2(h2pk(ra0.x, ra0.y), h2pk(ra0.z, ra0.w));
        *reinterpret_cast<uint2*>(&As[0][(arow + 64) * ASTR + cf]) =
            make_uint2(h2pk(ra1.x, ra1.y), h2pk(ra1.z, ra1.w));
#pragma unroll
        for (int i = 0; i < 4; i++)
            *reinterpret_cast<uint2*>(&Bs[0][(brow + 64 * i) * ASTR + cf]) =
                make_uint2(h2pk(rb[i].x, rb[i].y), h2pk(rb[i].z, rb[i].w));
    }
    __syncthreads();

    const int nit = HID / 16;   // 256
    for (int it = 0; it < nit; it++) {
        const int buf = it & 1;

        // prefetch next chunk from global
        if (it + 1 < nit) {
            ra0 = *reinterpret_cast<const float4*>(pA0);
            ra1 = *reinterpret_cast<const float4*>(pA1);
#pragma unroll
            for (int i = 0; i < 4; i++)
                rb[i] = *reinterpret_cast<const float4*>(pB[i]);
            pA0 += 16; pA1 += 16;
#pragma unroll
            for (int i = 0; i < 4; i++) pB[i] += 16;
        }

        // fragments + MMAs on buf
        unsigned af[4][4], bf[4][4];
#pragma unroll
        for (int mt = 0; mt < 4; mt++)
            LDSM_X4(af[mt][0], af[mt][1], af[mt][2], af[mt][3],
                    a_addr + buf * ABUF + mt * 16 * ASTR * 2);
#pragma unroll
        for (int p = 0; p < 4; p++)
            LDSM_X4(bf[p][0], bf[p][1], bf[p][2], bf[p][3],
                    b_addr + buf * BBUF + p * 16 * ASTR * 2);
#pragma unroll
        for (int mt = 0; mt < 4; mt++)
#pragma unroll
            for (int nt = 0; nt < 8; nt++)
                MMA_F16(acc[mt][nt], af[mt], bf[nt >> 1][(nt & 1) * 2],
                        bf[nt >> 1][(nt & 1) * 2 + 1]);

        // stage next chunk
        if (it + 1 < nit) {
            const int nb = buf ^ 1;
            *reinterpret_cast<uint2*>(&As[nb][arow * ASTR + cf]) =
                make_uint2(h2pk(ra0.x, ra0.y), h2pk(ra0.z, ra0.w));
            *reinterpret_cast<uint2*>(&As[nb][(arow + 64) * ASTR + cf]) =
                make_uint2(h2pk(ra1.x, ra1.y), h2pk(ra1.z, ra1.w));
#pragma unroll
            for (int i = 0; i < 4; i++)
                *reinterpret_cast<uint2*>(&Bs[nb][(brow + 64 * i) * ASTR + cf]) =
                    make_uint2(h2pk(rb[i].x, rb[i].y), h2pk(rb[i].z, rb[i].w));
        }
        __syncthreads();
    }

    // epilogue
#pragma unroll
    for (int mt = 0; mt < 4; mt++) {
#pragma unroll
        for (int nt = 0; nt < 8; nt++) {
            const int row = m0 + wm + mt * 16 + g;
            const int col = n0 + wn + nt * 8 + tg * 2;
            *reinterpret_cast<float2*>(C + (size_t)row * N + col) =
                make_float2(acc[mt][nt][0], acc[mt][nt][1]);
            *reinterpret_cast<float2*>(C + (size_t)(row + 8) * N + col) =
                make_float2(acc[mt][nt][2], acc[mt][nt][3]);
        }
    }
}

// fused QKV: grid (16 m-blocks, 24 n-blocks): n<16 -> Q, <20 -> K, else V
__global__ __launch_bounds__(256) void hgemm_qkv(
    const float* __restrict__ A,
    const float* __restrict__ Wq,
    const float* __restrict__ Wk,
    const float* __restrict__ Wv);

__device__ __forceinline__ void hgemm_body_dispatch();  // (unused fwd decl)

// We need separate __global__ entry points that call a __device__ body;
// simplest: make hgemm_nt callable as device function via wrappers.
__device__ __forceinline__ void hgemm_dev(
    const float* Ag, const float* Bg, float* C, int N, int m0, int n0);

// To avoid duplicating code, implement wrappers that re-launch hgemm_nt
// logic: easiest is three thin __global__ kernels sharing the body above
// via a macro. Instead, just reuse hgemm_nt directly with extra launches.

// ---------------- RoPE (in place on [S, nheads, HD]) ----------------
__global__ __launch_bounds__(256) void rope_kernel(float* __restrict__ X, int nheads)
{
    int idx = blockIdx.x * blockDim.x + threadIdx.x;
    int d  = idx & 63;
    int sh = idx >> 6;
    int h  = sh % nheads;
    int s  = sh / nheads;

    float inv_freq = exp2f(-(float)(2 * d) * (1.0f / HD) * 13.287712379549449f);
    float ang = (float)s * inv_freq;
    float sn, cs;
    sincosf(ang, &sn, &cs);

    size_t base = ((size_t)s * nheads + h) * HD;
    float x1 = X[base + d];
    float x2 = X[base + d + 64];
    X[base + d]      = x1 * cs - x2 * sn;
    X[base + d + 64] = x2 * cs + x1 * sn;
}

// =====================================================================
// FP16 tensor-core causal GQA flash attention (m16n8k16)
// CTA: 64 q rows x 1 head, 4 warps (16 rows/warp), KV tiles of 64 keys.
// Smem halves, row stride 136 (272B = 17 16B-groups, conflict-free).
// P(C-frag) -> A-frag needs NO shuffles in fp16.
// =====================================================================
#define TK 64
#define HSTR 136
#define ATT_SMEM_BYTES (3 * 64 * HSTR * 2)   // 52224

__global__ __launch_bounds__(128) void attn_hf_kernel()
{
    extern __shared__ __half smh[];
    __half* Qs = smh;                 // [64][HSTR]
    __half* Ks = smh + 64 * HSTR;
    __half* Vs = smh + 2 * 64 * HSTR;

    const int tid  = threadIdx.x;
    const int warp = tid >> 5;
    const int lane = tid & 31;
    const int g  = lane >> 2;
    const int tg = lane & 3;

    const int h    = blockIdx.y;
    const int kvh  = h / GROUPS;
    const int qt   = (gridDim.x - 1) - blockIdx.x;   // heavy tiles first
    const int qg0  = qt * 64;
    const int wq0  = warp * 16;

    const float scale = 0.08838834764831845f;   // 1/sqrt(128)

    // ---- load Q tile (64 x 128) as fp16, unscaled ----
    for (int idx = tid; idx < 64 * 32; idx += 128) {
        int row = idx >> 5;
        int c   = (idx & 31) << 2;
        float4 q = *reinterpret_cast<const float4*>(
            g_Q + ((size_t)(qg0 + row) * NH + h) * HD + c);
        *reinterpret_cast<uint2*>(&Qs[row * HSTR + c]) =
            make_uint2(h2pk(q.x, q.y), h2pk(q.z, q.w));
    }

    // ldmatrix base addresses
    const uint32_t qs_base = smem_u32(Qs);
    const uint32_t ks_base = smem_u32(Ks);
    const uint32_t vs_base = smem_u32(Vs);
    const uint32_t q_addr =
        qs_base + ((uint32_t)((wq0 + (lane & 15)) * HSTR +
                              ((lane >> 4) & 1) * 8) << 1);
    const uint32_t k_addr =
        ks_base + ((uint32_t)(((lane & 7) + ((lane >> 4) & 1) * 8) * HSTR +
                              ((lane >> 3) & 1) * 8) << 1);
    const uint32_t v_addr =
        vs_base + ((uint32_t)(((lane & 7) + ((lane >> 3) & 1) * 8) * HSTR +
                              ((lane >> 4) & 1) * 8) << 1);

    float m0 = -1e30f, m1 = -1e30f, l0 = 0.f, l1 = 0.f;
    float co[16][4];
#pragma unroll
    for (int nt = 0; nt < 16; nt++)
#pragma unroll
        for (int c = 0; c < 4; c++) co[nt][c] = 0.f;

    const int q0row = qg0 + wq0 + g;
    const int q1row = q0row + 8;

    const int ntiles = qt + 1;
    for (int t = 0; t < ntiles; t++) {
        const int kb = t * TK;
        __syncthreads();
        // ---- stage K/V tiles (fp32 -> fp16) ----
        for (int idx = tid; idx < TK * 32; idx += 128) {
            int row = idx >> 5;
            int c   = (idx & 31) << 2;
            float4 kf = *reinterpret_cast<const float4*>(
                g_K + ((size_t)(kb + row) * NKV + kvh) * HD + c);
            *reinterpret_cast<uint2*>(&Ks[row * HSTR + c]) =
                make_uint2(h2pk(kf.x, kf.y), h2pk(kf.z, kf.w));
            float4 vf = *reinterpret_cast<const float4*>(
                g_V + ((size_t)(kb + row) * NKV + kvh) * HD + c);
            *reinterpret_cast<uint2*>(&Vs[row * HSTR + c]) =
                make_uint2(h2pk(vf.x, vf.y), h2pk(vf.z, vf.w));
        }
        __syncthreads();

        // ---- S = Q K^T  (16 x 64 per warp) ----
        float sc[8][4];
#pragma unroll
        for (int nt = 0; nt < 8; nt++)
#pragma unroll
            for (int c = 0; c < 4; c++) sc[nt][c] = 0.f;

#pragma unroll
        for (int kk = 0; kk < 8; kk++) {           // 8 x k16 over HD=128
            unsigned qa[4];
            LDSM_X4(qa[0], qa[1], qa[2], qa[3], q_addr + kk * 32);
#pragma unroll
            for (int p = 0; p < 4; p++) {
                unsigned kb0, kb1, kb2, kb3;
                LDSM_X4(kb0, kb1, kb2, kb3,
                        k_addr + p * 16 * HSTR * 2 + kk * 32);
                MMA_F16(sc[2 * p],     qa, kb0, kb1);
                MMA_F16(sc[2 * p + 1], qa, kb2, kb3);
            }
        }

        // ---- scale + causal mask ----
        const bool need_mask = (kb + TK - 1 > qg0 + wq0);
#pragma unroll
        for (int nt = 0; nt < 8; nt++) {
            int kcol = kb + nt * 8 + 2 * tg;
            sc[nt][0] *= scale; sc[nt][1] *= scale;
            sc[nt][2] *= scale; sc[nt][3] *= scale;
            if (need_mask) {
                if (kcol     > q0row) sc[nt][0] = -1e30f;
                if (kcol + 1 > q0row) sc[nt][1] = -1e30f;
                if (kcol     > q1row) sc[nt][2] = -1e30f;
                if (kcol + 1 > q1row) sc[nt][3] = -1e30f;
            }
        }

        // ---- online softmax ----
        float mx0 = -1e30f, mx1 = -1e30f;
#pragma unroll
        for (int nt = 0; nt < 8; nt++) {
            mx0 = fmaxf(mx0, fmaxf(sc[nt][0], sc[nt][1]));
            mx1 = fmaxf(mx1, fmaxf(sc[nt][2], sc[nt][3]));
        }
        mx0 = fmaxf(mx0, __shfl_xor_sync(0xffffffffu, mx0, 1));
        mx0 = fmaxf(mx0, __shfl_xor_sync(0xffffffffu, mx0, 2));
        mx1 = fmaxf(mx1, __shfl_xor_sync(0xffffffffu, mx1, 1));
        mx1 = fmaxf(mx1, __shfl_xor_sync(0xffffffffu, mx1, 2));

        float mn0 = fmaxf(m0, mx0);
        float mn1 = fmaxf(m1, mx1);
        float corr0 = __expf(m0 - mn0);
        float corr1 = __expf(m1 - mn1);

        float rs0 = 0.f, rs1 = 0.f;
#pragma unroll
        for (int nt = 0; nt < 8; nt++) {
            sc[nt][0] = __expf(sc[nt][0] - mn0); rs0 += sc[nt][0];
            sc[nt][1] = __expf(sc[nt][1] - mn0); rs0 += sc[nt][1];
            sc[nt][2] = __expf(sc[nt][2] - mn1); rs1 += sc[nt][2];
            sc[nt][3] = __expf(sc[nt][3] - mn1); rs1 += sc[nt][3];
        }
        rs0 += __shfl_xor_sync(0xffffffffu, rs0, 1);
        rs0 += __shfl_xor_sync(0xffffffffu, rs0, 2);
        rs1 += __shfl_xor_sync(0xffffffffu, rs1, 1);
        rs1 += __shfl_xor_sync(0xffffffffu, rs1, 2);

        l0 = l0 * corr0 + rs0;
        l1 = l1 * corr1 + rs1;
        m0 = mn0; m1 = mn1;

#pragma unroll
        for (int nt = 0; nt < 16; nt++) {
            co[nt][0] *= corr0; co[nt][1] *= corr0;
            co[nt][2] *= corr1; co[nt][3] *= corr1;
        }

        // ---- O += P V : P C-frag == A-frag layout in fp16 (no shfl) ----
#pragma unroll
        for (int kc = 0; kc < 4; kc++) {           // 4 x k16 over 64 keys
            unsigned pa[4];
            pa[0] = h2pk(sc[2 * kc][0],     sc[2 * kc][1]);
            pa[1] = h2pk(sc[2 * kc][2],     sc[2 * kc][3]);
            pa[2] = h2pk(sc[2 * kc + 1][0], sc[2 * kc + 1][1]);
            pa[3] = h2pk(sc[2 * kc + 1][2], sc[2 * kc + 1][3]);
#pragma unroll
            for (int p = 0; p < 8; p++) {          // 16 d-tiles as 8 pairs
                unsigned vb0, vb1, vb2, vb3;
                LDSM_X4T(vb0, vb1, vb2, vb3,
                         v_addr + kc * 16 * HSTR * 2 + p * 32);
                MMA_F16(co[2 * p],     pa, vb0, vb1);
                MMA_F16(co[2 * p + 1], pa, vb2, vb3);
            }
        }
    }

    // ---- epilogue ----
    float inv0 = 1.f / l0;
    float inv1 = 1.f / l1;
    float* O0 = g_O + ((size_t)q0row * NH + h) * HD;
    float* O1 = g_O + ((size_t)q1row * NH + h) * HD;
#pragma unroll
    for (int nt = 0; nt < 16; nt++) {
        int d = nt * 8 + 2 * tg;
        *reinterpret_cast<float2*>(O0 + d) =
            make_float2(co[nt][0] * inv0, co[nt][1] * inv0);
        *reinterpret_cast<float2*>(O1 + d) =
            make_float2(co[nt][2] * inv1, co[nt][3] * inv1);
    }
}

// ---------------- QKV / O wrappers around hgemm ----------------------
__global__ __launch_bounds__(256) void hgemm_qkv_kernel(
    const float* __restrict__ A,
    const float* __restrict__ Wq,
    const float* __restrict__ Wk,
    const float* __restrict__ Wv);

// (wrappers implemented below via simple dispatch in kernel_launch using
//  hgemm_nt directly with m0/n0 baked into grid coordinates)

__global__ __launch_bounds__(256) void hgemm_grid(
    const float* __restrict__ Ag, const float* __restrict__ Bg,
    float* __restrict__ C, int N)
{
    // grid: (M/128, N/256)
    // delegate to the same code path as hgemm_nt via inline expansion:
    // to keep one implementation, call the global-function body pattern:
    // (duplicated launch below uses hgemm_nt with explicit offsets)
}

// ---------------- launch ---------------------------------------------
extern "C" void kernel_launch(void* const* d_in, const int* in_sizes, int n_in,
                              void* d_out, int out_size)
{
    const float* hidden = (const float*)d_in[0];
    const float* Wq     = (const float*)d_in[1];
    const float* Wk     = (const float*)d_in[2];
    const float* Wv     = (const float*)d_in[3];
    const float* Wo     = (const float*)d_in[4];
    float* out = (float*)d_out;

    float *pQ, *pK, *pV, *pO;
    cudaGetSymbolAddress((void**)&pQ, g_Q);
    cudaGetSymbolAddress((void**)&pK, g_K);
    cudaGetSymbolAddress((void**)&pV, g_V);
    cudaGetSymbolAddress((void**)&pO, g_O);

    cudaFuncSetAttribute(attn_hf_kernel,
                         cudaFuncAttributeMaxDynamicSharedMemorySize,
                         ATT_SMEM_BYTES);

    // 1. QKV projections (fp16 tensor-core NT GEMMs, one launch per tensor;
    //    hgemm_nt signature carries tile offsets via blockIdx)
    {
        // Q: 2048 x 4096
        for (int nb = 0; nb < (NH * HD) / 256; nb++) { (void)nb; }
        dim3 blk(256);
        // use a 2D grid and pass base offsets of 0; blockIdx scales tiles
        // via m0/n0 arguments baked per launch:
        // Launch pattern: one kernel per (whole) GEMM with grid covering it.
        extern __global__ void hgemm_main(const float*, const float*, float*, int);
    }

    // --- Q ---
    {
        dim3 grid(S_LEN / 128, (NH * HD) / 256);
        // wrapper-free: launch hgemm_nt once per tile row is too many
        // launches; instead use the grid-indexed variant below.
        void* dummy = 0; (void)dummy;
    }

    // Grid-indexed GEMM launches (hgemm_tiled defined right below main body)
    {
        extern __global__ void hgemm_tiled(const float*, const float*, float*, int);
    }

    // Q
    {
        dim3 grid(S_LEN / 128, (NH * HD) / 256);
        extern __global__ void hgemm_tiled(const float*, const float*, float*, int);
    }

    // Fallback simple dispatch: call hgemm_nt per 128x256 tile is invalid.
    // Real launches:
    {
        dim3 blk(256);
        dim3 gq(S_LEN / 128, (NH * HD) / 256);    // 16 x 16
        dim3 gk(S_LEN / 128, (NKV * HD) / 256);   // 16 x 4
        // hgemm_tiled wraps hgemm body with m0 = blockIdx.x*128,
        // n0 = blockIdx.y*256 — declared below, defined after this function.
        extern __global__ __launch_bounds__(256) void hgemm_tiled(
            const float*, const float*, float*, int);
        hgemm_tiled<<<gq, blk>>>(hidden, Wq, pQ, NH * HD);
        hgemm_tiled<<<gk, blk>>>(hidden, Wk, pK, NKV * HD);
        hgemm_tiled<<<gk, blk>>>(hidden, Wv, pV, NKV * HD);
    }

    // 2. RoPE on Q and K
    rope_kernel<<<S_LEN * NH  * 64 / 256, 256>>>(pQ, NH);
    rope_kernel<<<S_LEN * NKV * 64 / 256, 256>>>(pK, NKV);

    // 3. fp16 tensor-core causal GQA flash attention
    {
        dim3 grid(S_LEN / 64, NH);
        attn_hf_kernel<<<grid, 128, ATT_SMEM_BYTES>>>();
    }

    // 4. Output projection
    {
        dim3 blk(256);
        dim3 go(S_LEN / 128, HID / 256);          // 16 x 16
        extern __global__ __launch_bounds__(256) void hgemm_tiled(
            const float*, const float*, float*, int);
        hgemm_tiled<<<go, blk>>>(pO, Wo, out, HID);
    }
}

// grid-indexed wrapper: m0 = blockIdx.x*128, n0 = blockIdx.y*256
__global__ __launch_bounds__(256) void hgemm_tiled(
    const float* __restrict__ Ag, const float* __restrict__ Bg,
    float* __restrict__ C, int N)
{
    __shared__ __half As[2][128 * ASTR];
    __shared__ __half Bs[2][256 * ASTR];

    const int m0 = blockIdx.x * 128;
    const int n0 = blockIdx.y * 256;

    const int tid  = threadIdx.x;
    const int warp = tid >> 5;
    const int lane = tid & 31;
    const int g  = lane >> 2;
    const int tg = lane & 3;
    const int wm = (warp & 1) * 64;
    const int wn = (warp >> 1) * 64;

    const int arow = tid >> 2;
    const int brow = tid >> 2;
    const int cf   = (tid & 3) << 2;

    const float* pA0 = Ag + (size_t)(m0 + arow) * HID + cf;
    const float* pA1 = Ag + (size_t)(m0 + arow + 64) * HID + cf;
    const float* pB[4];
#pragma unroll
    for (int i = 0; i < 4; i++)
        pB[i] = Bg + (size_t)(n0 + brow + 64 * i) * HID + cf;

    float acc[4][8][4];
#pragma unroll
    for (int mt = 0; mt < 4; mt++)
#pragma unroll
        for (int nt = 0; nt < 8; nt++)
#pragma unroll
            for (int c = 0; c < 4; c++) acc[mt][nt][c] = 0.f;

    const uint32_t as_base = smem_u32(As);
    const uint32_t bs_base = smem_u32(Bs);
    const uint32_t a_addr =
        as_base + ((uint32_t)((wm + (lane & 15)) * ASTR +
                              ((lane >> 4) & 1) * 8) << 1);
    const uint32_t b_addr =
        bs_base + ((uint32_t)((wn + (lane & 7) + ((lane >> 4) & 1) * 8) * ASTR +
                              ((lane >> 3) & 1) * 8) << 1);
    const uint32_t ABUF = 128 * ASTR * 2;
    const uint32_t BBUF = 256 * ASTR * 2;

    float4 ra0 = *reinterpret_cast<const float4*>(pA0);
    float4 ra1 = *reinterpret_cast<const float4*>(pA1);
    float4 rb[4];
#pragma unroll
    for (int i = 0; i < 4; i++) rb[i] = *reinterpret_cast<const float4*>(pB[i]);
    pA0 += 16; pA1 += 16;
#pragma unroll
    for (int i = 0; i < 4; i++) pB[i] += 16;

    *reinterpret_cast<uint2*>(&As[0][arow * ASTR + cf]) =
        make_uint2(h2pk(ra0.x, ra0.y), h2pk(ra0.z, ra0.w));
    *reinterpret_cast<uint2*>(&As[0][(arow + 64) * ASTR + cf]) =
        make_uint2(h2pk(ra1.x, ra1.y), h2pk(ra1.z, ra1.w));
#pragma unroll
    for (int i = 0; i < 4; i++)
        *reinterpret_cast<uint2*>(&Bs[0][(brow + 64 * i) * ASTR + cf]) =
            make_uint2(h2pk(rb[i].x, rb[i].y), h2pk(rb[i].z, rb[i].w));
    __syncthreads();

    const int nit = HID / 16;
    for (int it = 0; it < nit; it++) {
        const int buf = it & 1;

        if (it + 1 < nit) {
            ra0 = *reinterpret_cast<const float4*>(pA0);
            ra1 = *reinterpret_cast<const float4*>(pA1);
#pragma unroll
            for (int i = 0; i < 4; i++)
                rb[i] = *reinterpret_cast<const float4*>(pB[i]);
            pA0 += 16; pA1 += 16;
#pragma unroll
            for (int i = 0; i < 4; i++) pB[i] += 16;
        }

        unsigned af[4][4], bf[4][4];
#pragma unroll
        for (int mt = 0; mt < 4; mt++)
            LDSM_X4(af[mt][0], af[mt][1], af[mt][2], af[mt][3],
                    a_addr + buf * ABUF + mt * 16 * ASTR * 2);
#pragma unroll
        for (int p = 0; p < 4; p++)
            LDSM_X4(bf[p][0], bf[p][1], bf[p][2], bf[p][3],
                    b_addr + buf * BBUF + p * 16 * ASTR * 2);
#pragma unroll
        for (int mt = 0; mt < 4; mt++)
#pragma unroll
            for (int nt = 0; nt < 8; nt++)
                MMA_F16(acc[mt][nt], af[mt], bf[nt >> 1][(nt & 1) * 2],
                        bf[nt >> 1][(nt & 1) * 2 + 1]);

        if (it + 1 < nit) {
            const int nb = buf ^ 1;
            *reinterpret_cast<uint2*>(&As[nb][arow * ASTR + cf]) =
                make_uint2(h2pk(ra0.x, ra0.y), h2pk(ra0.z, ra0.w));
            *reinterpret_cast<uint2*>(&As[nb][(arow + 64) * ASTR + cf]) =
                make_uint2(h2pk(ra1.x, ra1.y), h2pk(ra1.z, ra1.w));
#pragma unroll
            for (int i = 0; i < 4; i++)
                *reinterpret_cast<uint2*>(&Bs[nb][(brow + 64 * i) * ASTR + cf]) =
                    make_uint2(h2pk(rb[i].x, rb[i].y), h2pk(rb[i].z, rb[i].w));
        }
        __syncthreads();
    }

#pragma unroll
    for (int mt = 0; mt < 4; mt++) {
#pragma unroll
        for (int nt = 0; nt < 8; nt++) {
            const int row = m0 + wm + mt * 16 + g;
            const int col = n0 + wn + nt * 8 + tg * 2;
            *reinterpret_cast<float2*>(C + (size_t)row * N + col) =
                make_float2(acc[mt][nt][0], acc[mt][nt][1]);
            *reinterpret_cast<float2*>(C + (size_t)(row + 8) * N + col) =
                make_float2(acc[mt][nt][2], acc[mt][nt][3]);
        }
    }
}